// round 12
// baseline (speedup 1.0000x reference)
#include <cuda_runtime.h>
#include <cuda_fp16.h>
#include <cstdint>
#include <math.h>

// ---------------- problem constants ----------------
#define NSYM   200001
#define PADID  200000
#define BQ     1024
#define FEW    5
#define NB     200
#define DM     256
#define DI     512
#define HID    512
#define G4     2048
#define NROWS  (BQ + FEW)

typedef __half fp16;

// ---------------- device scratch ----------------
__device__ fp16  g_projh[(size_t)NSYM * 256];
__device__ fp16  g_Wph[256 * 128];
__device__ fp16  g_p1h[512 * 256];
__device__ fp16  g_p2h[256 * 512];
__device__ fp16  g_Wihh[2048 * 256];   // gate-interleaved rows: new_row = j*4+g
__device__ fp16  g_Whhh[2048 * 256];   // gate-interleaved rows (cols 0..255 of Whh)
__device__ float g_biasproj[256];
__device__ float g_bsum[G4];           // gate-interleaved
__device__ float g_xcat[NROWS * DM];
__device__ fp16  g_xcath[NROWS * DM];
__device__ fp16  g_hench[NROWS * DI];
__device__ float g_oenc[NROWS * DM];
__device__ float g_enc[NROWS * DM];
__device__ fp16  g_ench[NROWS * DM];
__device__ float g_support[DM];
__device__ float g_sconst[G4];         // gate-interleaved
__device__ float g_qWihb[BQ * G4];     // gate-interleaved cols
__device__ float g_h[BQ * DM];
__device__ fp16  g_hh[BQ * DM];
__device__ float g_c[BQ * HID];
__device__ int   g_is64;

// ---------------- helpers ----------------
__device__ __forceinline__ uint32_t smem_u32(const void* p) {
    uint32_t a;
    asm("{ .reg .u64 t; cvta.to.shared.u64 t, %1; cvt.u32.u64 %0, t; }" : "=r"(a) : "l"(p));
    return a;
}
__device__ __forceinline__ void ldmatrix4(uint32_t addr, uint32_t& r0, uint32_t& r1,
                                          uint32_t& r2, uint32_t& r3) {
    asm volatile("ldmatrix.sync.aligned.m8n8.x4.shared.b16 {%0,%1,%2,%3}, [%4];"
                 : "=r"(r0), "=r"(r1), "=r"(r2), "=r"(r3) : "r"(addr));
}
__device__ __forceinline__ void mma16816(float* d, const uint32_t* a,
                                         uint32_t b0, uint32_t b1) {
    asm volatile(
        "mma.sync.aligned.m16n8k16.row.col.f32.f16.f16.f32 "
        "{%0,%1,%2,%3}, {%4,%5,%6,%7}, {%8,%9}, {%0,%1,%2,%3};"
        : "+f"(d[0]), "+f"(d[1]), "+f"(d[2]), "+f"(d[3])
        : "r"(a[0]), "r"(a[1]), "r"(a[2]), "r"(a[3]), "r"(b0), "r"(b1));
}
__device__ __forceinline__ uint32_t pack_h2(fp16 a, fp16 b) {
    __half2 t(a, b);
    return *reinterpret_cast<uint32_t*>(&t);
}
__device__ __forceinline__ uint4 cvt8(const float* f) {
    return make_uint4(pack_h2(__float2half(f[0]), __float2half(f[1])),
                      pack_h2(__float2half(f[2]), __float2half(f[3])),
                      pack_h2(__float2half(f[4]), __float2half(f[5])),
                      pack_h2(__float2half(f[6]), __float2half(f[7])));
}
__device__ __forceinline__ float sigm(float x) { return 1.f / (1.f + expf(-x)); }

// ---------------- fused prep ----------------
#define T8_P1 (512 * 256 / 8)
#define T8_P2 (256 * 512 / 8)
#define T8_WI (2048 * 256 / 8)
#define T8_WH (2048 * 256 / 8)
#define T8_ALL (T8_P1 + T8_P2 + T8_WI + T8_WH)

__global__ void prep_all_kernel(const float* __restrict__ gcnW,
                                const float* __restrict__ wb,
                                const float* __restrict__ gb,
                                const float* __restrict__ bih,
                                const float* __restrict__ bhh,
                                const int* __restrict__ qlc_i32,
                                const float* __restrict__ p1W,
                                const float* __restrict__ p2W,
                                const float* __restrict__ Wih,
                                const float* __restrict__ Whh) {
    int idx = blockIdx.x * blockDim.x + threadIdx.x;
    if (idx == 0) {
        int any = 0;
        for (int i = 1; i < 2 * NB; i += 2) any |= qlc_i32[i];
        g_is64 = (any == 0) ? 1 : 0;
    }
    if (idx < 256 * 128) {
        int j = idx >> 7, e = idx & 127;
        float v = (j < 128) ? gcnW[j * 256 + e] : gcnW[(j - 128) * 256 + 128 + e];
        g_Wph[idx] = __float2half(v);
    }
    if (idx < 256) g_biasproj[idx] = (idx < 128) ? (wb[idx] + gb[idx]) : 0.f;
    if (idx < G4) {   // gate-interleaved bias
        int old = (idx & 3) * 512 + (idx >> 2);
        g_bsum[idx] = bih[old] + bhh[old];
    }

    if (idx < T8_ALL) {
        const float* src;
        fp16* dst;
        int e0;
        if (idx < T8_P1) {
            e0 = idx * 8; src = p1W + e0; dst = g_p1h + e0;
        } else if (idx < T8_P1 + T8_P2) {
            e0 = (idx - T8_P1) * 8; src = p2W + e0; dst = g_p2h + e0;
        } else if (idx < T8_P1 + T8_P2 + T8_WI) {
            e0 = (idx - T8_P1 - T8_P2) * 8;
            int rn = e0 >> 8, col = e0 & 255;
            int ro = (rn & 3) * 512 + (rn >> 2);       // gate-interleave
            src = Wih + (size_t)ro * 256 + col;
            dst = g_Wihh + e0;
        } else {
            e0 = (idx - T8_P1 - T8_P2 - T8_WI) * 8;
            int rn = e0 >> 8, col = e0 & 255;
            int ro = (rn & 3) * 512 + (rn >> 2);
            src = Whh + (size_t)ro * 512 + col;        // cols 0..255 of ldw=512
            dst = g_Whhh + e0;
        }
        float4 v0 = *reinterpret_cast<const float4*>(src);
        float4 v1 = *reinterpret_cast<const float4*>(src + 4);
        float f[8] = {v0.x, v0.y, v0.z, v0.w, v1.x, v1.y, v1.z, v1.w};
        *reinterpret_cast<uint4*>(dst) = cvt8(f);
    }
}

// =====================================================================
// proj_mma: g_projh[NSYM,256] = fp16(emb @ Wproj^T + bias)
// =====================================================================
#define ROWB 272
#define PA_OFF 0
#define PB_OFF (128 * ROWB)
#define PROJ_SMEM (PB_OFF + 256 * ROWB)   // 104448

__global__ void __launch_bounds__(256, 2)
proj_mma_kernel(const float* __restrict__ emb) {
    extern __shared__ char sm[];
    const uint32_t sbase = smem_u32(sm);
    const int tid = threadIdx.x;
    const int mbase = blockIdx.x * 128;

#pragma unroll
    for (int i = 0; i < 8; ++i) {
        int c = tid + i * 256;
        int row = c >> 4, ch = c & 15;
        int grow = mbase + row;
        uint4 h = make_uint4(0, 0, 0, 0);
        if (grow < NSYM) {
            const float* p = emb + (size_t)grow * 128 + ch * 8;
            float4 v0 = *reinterpret_cast<const float4*>(p);
            float4 v1 = *reinterpret_cast<const float4*>(p + 4);
            float f[8] = {v0.x, v0.y, v0.z, v0.w, v1.x, v1.y, v1.z, v1.w};
            h = cvt8(f);
        }
        *reinterpret_cast<uint4*>(sm + PA_OFF + row * ROWB + ch * 16) = h;
    }
#pragma unroll
    for (int i = 0; i < 16; ++i) {
        int c = tid + i * 256;
        int row = c >> 4, ch = c & 15;
        uint4 h = *reinterpret_cast<const uint4*>(g_Wph + row * 128 + ch * 8);
        *reinterpret_cast<uint4*>(sm + PB_OFF + row * ROWB + ch * 16) = h;
    }
    __syncthreads();

    const int warp = tid >> 5, lane = tid & 31;
    const int wm = warp & 3, wn = warp >> 2;
    const int m0 = wm * 32, n0 = wn * 64;

    const int a_row = (lane & 15);
    const int a_kadd = (lane >> 4) << 3;
    const int b_row = ((lane >> 4) << 3) + (lane & 7);
    const int b_kadd = ((lane >> 3) & 1) << 3;

    for (int half = 0; half < 2; ++half) {
        const uint32_t bofs = PB_OFF + half * 128 * ROWB;

        float acc[2][8][4];
#pragma unroll
        for (int i = 0; i < 2; ++i)
#pragma unroll
            for (int j = 0; j < 8; ++j)
#pragma unroll
                for (int q = 0; q < 4; ++q) acc[i][j][q] = 0.f;

#pragma unroll
        for (int ks = 0; ks < 8; ++ks) {
            const int k0 = ks * 16;
            uint32_t ra[2][4];
#pragma unroll
            for (int mi = 0; mi < 2; ++mi)
                ldmatrix4(sbase + PA_OFF + (m0 + mi * 16 + a_row) * ROWB + (k0 + a_kadd) * 2,
                          ra[mi][0], ra[mi][1], ra[mi][2], ra[mi][3]);
            uint32_t rb[4][4];
#pragma unroll
            for (int np = 0; np < 4; ++np)
                ldmatrix4(sbase + bofs + (n0 + np * 16 + b_row) * ROWB + (k0 + b_kadd) * 2,
                          rb[np][0], rb[np][1], rb[np][2], rb[np][3]);
#pragma unroll
            for (int mi = 0; mi < 2; ++mi)
#pragma unroll
                for (int ni = 0; ni < 8; ++ni)
                    mma16816(acc[mi][ni], ra[mi],
                             rb[ni >> 1][(ni & 1) * 2 + 0], rb[ni >> 1][(ni & 1) * 2 + 1]);
        }

        const int rbase = mbase + m0;
#pragma unroll
        for (int mi = 0; mi < 2; ++mi) {
#pragma unroll
            for (int ni = 0; ni < 8; ++ni) {
                int gcol = half * 128 + n0 + ni * 8 + (lane & 3) * 2;
                float b0 = g_biasproj[gcol], b1 = g_biasproj[gcol + 1];
                int r0 = rbase + mi * 16 + (lane >> 2);
                int r1 = r0 + 8;
                if (r0 < NSYM)
                    *reinterpret_cast<uint32_t*>(g_projh + (size_t)r0 * 256 + gcol) =
                        pack_h2(__float2half(acc[mi][ni][0] + b0),
                                __float2half(acc[mi][ni][1] + b1));
                if (r1 < NSYM)
                    *reinterpret_cast<uint32_t*>(g_projh + (size_t)r1 * 256 + gcol) =
                        pack_h2(__float2half(acc[mi][ni][2] + b0),
                                __float2half(acc[mi][ni][3] + b1));
            }
        }
    }
}

// =====================================================================
// hgemm_small: 64(M) x 128(N) tile, 128 threads, generic epilogue.
// =====================================================================
#define KROWB 144
#define HS_A  0
#define HS_B  (64 * KROWB)
#define HS_SMEM ((64 + 128) * KROWB)   // 27648

// core mainloop shared by both small-gemm kernels (as a macro-free inline)
template<int DO_LSTM>
__device__ __forceinline__ void hgemm_core(
    int M, int N, int K,
    const fp16* __restrict__ A, const fp16* __restrict__ B,
    char* sm, uint32_t sbase, int mtile, int ntile,
    float acc[2][8][4]) {
    const int tid = threadIdx.x;
    const int warp = tid >> 5, lane = tid & 31;
    const int wm = warp & 1, wn = warp >> 1;
    const int m0 = wm * 32, n0 = wn * 64;

    const int a_row = (lane & 15);
    const int a_kadd = (lane >> 4) << 3;
    const int b_row = ((lane >> 4) << 3) + (lane & 7);
    const int b_kadd = ((lane >> 3) & 1) << 3;

    for (int kc = 0; kc < K; kc += 64) {
#pragma unroll
        for (int i = 0; i < 4; ++i) {
            int c = tid + i * 128;
            int row = c >> 3, ch = c & 7;
            int grow = mtile + row;
            uint4 h = make_uint4(0, 0, 0, 0);
            if (grow < M)
                h = *reinterpret_cast<const uint4*>(A + (size_t)grow * K + kc + ch * 8);
            *reinterpret_cast<uint4*>(sm + HS_A + row * KROWB + ch * 16) = h;
        }
#pragma unroll
        for (int i = 0; i < 8; ++i) {
            int c = tid + i * 128;
            int row = c >> 3, ch = c & 7;
            int grow = ntile + row;
            uint4 h = *reinterpret_cast<const uint4*>(B + (size_t)grow * K + kc + ch * 8);
            *reinterpret_cast<uint4*>(sm + HS_B + row * KROWB + ch * 16) = h;
        }
        __syncthreads();

#pragma unroll
        for (int ks = 0; ks < 4; ++ks) {
            const int k0 = ks * 16;
            uint32_t ra[2][4];
#pragma unroll
            for (int mi = 0; mi < 2; ++mi)
                ldmatrix4(sbase + HS_A + (m0 + mi * 16 + a_row) * KROWB + (k0 + a_kadd) * 2,
                          ra[mi][0], ra[mi][1], ra[mi][2], ra[mi][3]);
            uint32_t rb[4][4];
#pragma unroll
            for (int np = 0; np < 4; ++np)
                ldmatrix4(sbase + HS_B + (n0 + np * 16 + b_row) * KROWB + (k0 + b_kadd) * 2,
                          rb[np][0], rb[np][1], rb[np][2], rb[np][3]);
#pragma unroll
            for (int mi = 0; mi < 2; ++mi)
#pragma unroll
                for (int ni = 0; ni < 8; ++ni)
                    mma16816(acc[mi][ni], ra[mi],
                             rb[ni >> 1][(ni & 1) * 2 + 0], rb[ni >> 1][(ni & 1) * 2 + 1]);
        }
        __syncthreads();
    }
}

__global__ void __launch_bounds__(128, 4)
hgemm_small(int M, int N, int K,
            const fp16* __restrict__ A, const fp16* __restrict__ B,
            const float* __restrict__ bias, const float* __restrict__ addMat,
            float* __restrict__ C, fp16* __restrict__ Chi, int doRelu) {
    extern __shared__ char sm[];
    const uint32_t sbase = smem_u32(sm);
    const int mtile = blockIdx.y * 64, ntile = blockIdx.x * 128;
    float acc[2][8][4];
#pragma unroll
    for (int i = 0; i < 2; ++i)
#pragma unroll
        for (int j = 0; j < 8; ++j)
#pragma unroll
            for (int q = 0; q < 4; ++q) acc[i][j][q] = 0.f;

    hgemm_core<0>(M, N, K, A, B, sm, sbase, mtile, ntile, acc);

    const int tid = threadIdx.x;
    const int warp = tid >> 5, lane = tid & 31;
    const int wm = warp & 1, wn = warp >> 1;
    const int m0 = wm * 32, n0 = wn * 64;

#pragma unroll
    for (int mi = 0; mi < 2; ++mi) {
#pragma unroll
        for (int ni = 0; ni < 8; ++ni) {
            int col = ntile + n0 + ni * 8 + (lane & 3) * 2;
            float b0 = bias ? bias[col] : 0.f;
            float b1 = bias ? bias[col + 1] : 0.f;
#pragma unroll
            for (int half = 0; half < 2; ++half) {
                int r = mtile + m0 + mi * 16 + (lane >> 2) + half * 8;
                if (r >= M) continue;
                float vx = acc[mi][ni][half * 2 + 0] + b0;
                float vy = acc[mi][ni][half * 2 + 1] + b1;
                if (addMat) {
                    vx += addMat[(size_t)r * N + col];
                    vy += addMat[(size_t)r * N + col + 1];
                }
                if (doRelu) { vx = fmaxf(vx, 0.f); vy = fmaxf(vy, 0.f); }
                if (C)
                    *reinterpret_cast<float2*>(C + (size_t)r * N + col) = make_float2(vx, vy);
                if (Chi)
                    *reinterpret_cast<uint32_t*>(Chi + (size_t)r * N + col) =
                        pack_h2(__float2half(vx), __float2half(vy));
            }
        }
    }
}

// =====================================================================
// hgemm_lstm: gates GEMM with fused LSTM epilogue (gate-interleaved cols)
// A = g_hh [1024,256], B = g_Whhh [2048,256]; bias=sconst, add=qWihb.
// Epilogue: assemble (i,f,g,o) per j via lane-quad shuffle, update c/h.
// =====================================================================
__global__ void __launch_bounds__(128, 4)
hgemm_lstm(int writeH) {
    extern __shared__ char sm[];
    const uint32_t sbase = smem_u32(sm);
    const int mtile = blockIdx.y * 64, ntile = blockIdx.x * 128;
    float acc[2][8][4];
#pragma unroll
    for (int i = 0; i < 2; ++i)
#pragma unroll
        for (int j = 0; j < 8; ++j)
#pragma unroll
            for (int q = 0; q < 4; ++q) acc[i][j][q] = 0.f;

    hgemm_core<1>(BQ, G4, DM, g_hh, g_Whhh, sm, sbase, mtile, ntile, acc);

    const int tid = threadIdx.x;
    const int warp = tid >> 5, lane = tid & 31;
    const int wm = warp & 1, wn = warp >> 1;
    const int m0 = wm * 32, n0 = wn * 64;
    const int d = lane & 3;

#pragma unroll
    for (int mi = 0; mi < 2; ++mi) {
#pragma unroll
        for (int ni = 0; ni < 8; ++ni) {
            int colbase = ntile + n0 + ni * 8;
            int col = colbase + d * 2;
            float b0 = g_sconst[col], b1 = g_sconst[col + 1];
#pragma unroll
            for (int half = 0; half < 2; ++half) {
                int r = mtile + m0 + mi * 16 + (lane >> 2) + half * 8;   // always < 1024
                float vx = acc[mi][ni][half * 2 + 0] + b0 +
                           g_qWihb[(size_t)r * G4 + col];
                float vy = acc[mi][ni][half * 2 + 1] + b1 +
                           g_qWihb[(size_t)r * G4 + col + 1];
                float px = __shfl_xor_sync(0xffffffffu, vx, 1);
                float py = __shfl_xor_sync(0xffffffffu, vy, 1);
                if ((d & 1) == 0) {
                    int j = (colbase >> 2) + (d >> 1);
                    // vx=i, vy=f, px=g, py=o
                    float c_old = g_c[r * HID + j];
                    float cn = sigm(vy) * c_old + sigm(vx) * tanhf(px);
                    g_c[r * HID + j] = cn;
                    if (j < DM) {
                        float hv = g_enc[r * DM + j] + sigm(py) * tanhf(cn);
                        g_hh[r * DM + j] = __float2half(hv);
                        if (writeH) g_h[r * DM + j] = hv;
                    }
                }
            }
        }
    }
}

// ---------------- neighbor encoder: half2 full-line gather, split-k ----
__global__ void __launch_bounds__(128)
neighbor_kernel(const void* qlc, const void* qrc, const void* slc, const void* src) {
    __shared__ int sidx[2 * NB];
    __shared__ float redA[128];
    int b = blockIdx.x;
    const void* conn;
    int node, off;
    if (b < BQ)                { conn = qlc; node = b;                off = node * DM; }
    else if (b < 2 * BQ)       { conn = qrc; node = b - BQ;           off = node * DM + 128; }
    else if (b < 2 * BQ + FEW) { conn = slc; node = b - 2 * BQ;       off = (BQ + node) * DM; }
    else                       { conn = src; node = b - 2 * BQ - FEW; off = (BQ + node) * DM + 128; }

    int tid = threadIdx.x;
    size_t base = (size_t)node * (2 * NB);
    if (g_is64) {
        const long long* p = (const long long*)conn;
        for (int t = tid; t < 2 * NB; t += 128) sidx[t] = (int)p[base + t];
    } else {
        const int* p = (const int*)conn;
        for (int t = tid; t < 2 * NB; t += 128) sidx[t] = p[base + t];
    }
    __syncthreads();

    const fp16* __restrict__ proj = g_projh;
    const int grp = tid >> 6;
    const int c2 = (tid & 63) * 2;

    float m0 = -INFINITY, m1 = -INFINITY;
    for (int k = grp; k < NB; k += 2) {
        int rel = sidx[2 * k], ent = sidx[2 * k + 1];
        if (rel == PADID || ent == PADID) continue;
        __half2 a = *reinterpret_cast<const __half2*>(proj + (size_t)rel * 256 + c2);
        __half2 e = *reinterpret_cast<const __half2*>(proj + (size_t)ent * 256 + 128 + c2);
        float v0 = __half2float(__low2half(a)) + __half2float(__low2half(e));
        float v1 = __half2float(__high2half(a)) + __half2float(__high2half(e));
        v0 = (v0 > 0.f) ? v0 : 0.1f * v0;
        v1 = (v1 > 0.f) ? v1 : 0.1f * v1;
        m0 = fmaxf(m0, v0);
        m1 = fmaxf(m1, v1);
    }

    if (grp == 0) { redA[c2] = m0; redA[c2 + 1] = m1; }
    __syncthreads();
    if (grp == 1) {
        float f0 = tanhf(fmaxf(m0, redA[c2]));
        float f1 = tanhf(fmaxf(m1, redA[c2 + 1]));
        *reinterpret_cast<float2*>(g_xcat + off + c2) = make_float2(f0, f1);
        *reinterpret_cast<uint32_t*>(g_xcath + off + c2) =
            pack_h2(__float2half(f0), __float2half(f1));
    }
}

// ---------------- layernorm ----------------
__global__ void ln_kernel(const float* __restrict__ lg, const float* __restrict__ lb) {
    __shared__ float red[256];
    int row = blockIdx.x, t = threadIdx.x;
    float v = g_oenc[row * DM + t];
    red[t] = v;
    __syncthreads();
    for (int s = 128; s > 0; s >>= 1) { if (t < s) red[t] += red[t + s]; __syncthreads(); }
    float mu = red[0] * (1.f / 256.f);
    __syncthreads();
    float d = v - mu;
    red[t] = d * d;
    __syncthreads();
    for (int s = 128; s > 0; s >>= 1) { if (t < s) red[t] += red[t + s]; __syncthreads(); }
    float var = red[0] * (1.f / 256.f);
    float o = d * rsqrtf(var + 1e-5f) * lg[t] + lb[t];
    g_enc[row * DM + t] = o;
    g_ench[row * DM + t] = __float2half(o);
}

// ---------------- fused mean + sconst (writes gate-interleaved) ----------
__global__ void sconst2_kernel(const float* __restrict__ Whh) {
    __shared__ float sup[256];
    int t = threadIdx.x;
    float s = 0.f;
    for (int r = 0; r < FEW; ++r) s += g_enc[(BQ + r) * DM + t];
    s *= (1.f / FEW);
    sup[t] = s;
    if (blockIdx.x == 0) g_support[t] = s;
    __syncthreads();

    int warp = t >> 5, lane = t & 31;
#pragma unroll
    for (int gi = 0; gi < 4; ++gi) {
        int go = blockIdx.x * 32 + warp * 4 + gi;   // old gate index
        float acc = 0.f;
        for (int i = lane; i < DM; i += 32)
            acc += sup[i] * Whh[(size_t)go * 512 + 256 + i];
#pragma unroll
        for (int o = 16; o > 0; o >>= 1) acc += __shfl_down_sync(0xffffffffu, acc, o);
        if (lane == 0) g_sconst[(go & 511) * 4 + (go >> 9)] = acc;
    }
}

// ---------------- LSTM step 1 (h_r = 0): coalesced float4 gate reads -------
__global__ void lstm1_kernel() {
    int idx = blockIdx.x * blockDim.x + threadIdx.x;
    if (idx >= BQ * HID) return;
    int n = idx >> 9, j = idx & 511;
    float4 gv = *reinterpret_cast<const float4*>(g_qWihb + (size_t)n * G4 + j * 4);
    // gv = (i, f, g, o); c_prev = 0
    float cn = sigm(gv.x) * tanhf(gv.z);
    g_c[idx] = cn;
    if (j < DM) {
        float hv = g_enc[n * DM + j] + sigm(gv.w) * tanhf(cn);
        g_hh[n * DM + j] = __float2half(hv);
    }
}

// ---------------- final dot ----------------
__global__ void final_kernel(float* __restrict__ out) {
    int n = (blockIdx.x * blockDim.x + threadIdx.x) >> 5;
    int lane = threadIdx.x & 31;
    if (n >= BQ) return;
    float s = 0.f;
    for (int i = lane; i < DM; i += 32)
        s += g_h[n * DM + i] * g_support[i];
#pragma unroll
    for (int o = 16; o > 0; o >>= 1) s += __shfl_down_sync(0xffffffffu, s, o);
    if (lane == 0) out[n] = s;
}

// ---------------- launch ----------------
extern "C" void kernel_launch(void* const* d_in, const int* in_sizes, int n_in,
                              void* d_out, int out_size) {
    const void* qlc = d_in[0];
    const void* qrc = d_in[1];
    const void* slc = d_in[2];
    const void* src = d_in[3];
    const float* emb  = (const float*)d_in[8];
    const float* gcnW = (const float*)d_in[9];
    const float* wb   = (const float*)d_in[10];
    const float* gb   = (const float*)d_in[11];
    const float* p1W  = (const float*)d_in[12];
    const float* p1b  = (const float*)d_in[13];
    const float* p2W  = (const float*)d_in[14];
    const float* p2b  = (const float*)d_in[15];
    const float* lng  = (const float*)d_in[16];
    const float* lnb  = (const float*)d_in[17];
    const float* Wih  = (const float*)d_in[18];
    const float* Whh  = (const float*)d_in[19];
    const float* bih  = (const float*)d_in[20];
    const float* bhh  = (const float*)d_in[21];

    fp16 *p1h, *p2h, *Wihh, *xcath, *hench, *ench;
    float *xcat, *oenc, *qWihb, *bsum;
    cudaGetSymbolAddress((void**)&p1h,    g_p1h);
    cudaGetSymbolAddress((void**)&p2h,    g_p2h);
    cudaGetSymbolAddress((void**)&Wihh,   g_Wihh);
    cudaGetSymbolAddress((void**)&xcath,  g_xcath);
    cudaGetSymbolAddress((void**)&hench,  g_hench);
    cudaGetSymbolAddress((void**)&ench,   g_ench);
    cudaGetSymbolAddress((void**)&xcat,   g_xcat);
    cudaGetSymbolAddress((void**)&oenc,   g_oenc);
    cudaGetSymbolAddress((void**)&qWihb,  g_qWihb);
    cudaGetSymbolAddress((void**)&bsum,   g_bsum);

    prep_all_kernel<<<(T8_ALL + 255) / 256, 256>>>(
        gcnW, wb, gb, bih, bhh, (const int*)qlc, p1W, p2W, Wih, Whh);

    cudaFuncSetAttribute(proj_mma_kernel,
                         cudaFuncAttributeMaxDynamicSharedMemorySize, PROJ_SMEM);
    proj_mma_kernel<<<(NSYM + 127) / 128, 256, PROJ_SMEM>>>(emb);

    neighbor_kernel<<<2 * BQ + 2 * FEW, 128>>>(qlc, qrc, slc, src);

    cudaFuncSetAttribute(hgemm_small,
                         cudaFuncAttributeMaxDynamicSharedMemorySize, HS_SMEM);
    cudaFuncSetAttribute(hgemm_lstm,
                         cudaFuncAttributeMaxDynamicSharedMemorySize, HS_SMEM);

    // support encoder
    hgemm_small<<<dim3(512 / 128, (NROWS + 63) / 64), 128, HS_SMEM>>>(
        NROWS, 512, 256, xcath, p1h, p1b, nullptr, nullptr, hench, 1);
    hgemm_small<<<dim3(256 / 128, (NROWS + 63) / 64), 128, HS_SMEM>>>(
        NROWS, 256, 512, hench, p2h, p2b, xcat, oenc, nullptr, 0);
    ln_kernel<<<NROWS, 256>>>(lng, lnb);

    sconst2_kernel<<<G4 / 32, 256>>>(Whh);

    // qWihb = enc@Wih'^T + bsum'  (gate-interleaved)
    hgemm_small<<<dim3(G4 / 128, BQ / 64), 128, HS_SMEM>>>(
        BQ, G4, 256, ench, Wihh, bsum, nullptr, qWihb, nullptr, 0);

    // step 1 (c=0): elementwise from qWihb
    lstm1_kernel<<<(BQ * HID + 255) / 256, 256>>>();

    // steps 2..4: gates GEMM with fused LSTM epilogue
    hgemm_lstm<<<dim3(G4 / 128, BQ / 64), 128, HS_SMEM>>>(0);
    hgemm_lstm<<<dim3(G4 / 128, BQ / 64), 128, HS_SMEM>>>(0);
    hgemm_lstm<<<dim3(G4 / 128, BQ / 64), 128, HS_SMEM>>>(1);

    final_kernel<<<(BQ * 32 + 255) / 256, 256>>>((float*)d_out);
}

// round 13
// speedup vs baseline: 1.2022x; 1.2022x over previous
#include <cuda_runtime.h>
#include <cuda_fp16.h>
#include <cstdint>
#include <math.h>

// ---------------- problem constants ----------------
#define NSYM   200001
#define PADID  200000
#define BQ     1024
#define FEW    5
#define NB     200
#define DM     256
#define DI     512
#define HID    512
#define G4     2048
#define NROWS  (BQ + FEW)

typedef __half fp16;

// ---------------- device scratch ----------------
__device__ fp16  g_projh[(size_t)NSYM * 256];
__device__ fp16  g_Wph[256 * 128];
__device__ fp16  g_p1h[512 * 256];
__device__ fp16  g_p2h[256 * 512];
__device__ fp16  g_Wihh[2048 * 256];
__device__ fp16  g_Whhh[2048 * 256];
__device__ float g_biasproj[256];
__device__ float g_bsum[G4];
__device__ float g_xcat[NROWS * DM];
__device__ fp16  g_xcath[NROWS * DM];
__device__ fp16  g_hench[NROWS * DI];
__device__ float g_oenc[NROWS * DM];
__device__ float g_enc[NROWS * DM];
__device__ fp16  g_ench[NROWS * DM];
__device__ float g_support[DM];
__device__ float g_sconst[G4];
__device__ float g_qWihb[BQ * G4];
__device__ float g_gates[BQ * G4];
__device__ fp16  g_hh[BQ * DM];
__device__ float g_c[BQ * HID];
__device__ int   g_is64;

// ---------------- helpers ----------------
__device__ __forceinline__ uint32_t smem_u32(const void* p) {
    uint32_t a;
    asm("{ .reg .u64 t; cvta.to.shared.u64 t, %1; cvt.u32.u64 %0, t; }" : "=r"(a) : "l"(p));
    return a;
}
__device__ __forceinline__ void ldmatrix4(uint32_t addr, uint32_t& r0, uint32_t& r1,
                                          uint32_t& r2, uint32_t& r3) {
    asm volatile("ldmatrix.sync.aligned.m8n8.x4.shared.b16 {%0,%1,%2,%3}, [%4];"
                 : "=r"(r0), "=r"(r1), "=r"(r2), "=r"(r3) : "r"(addr));
}
__device__ __forceinline__ void mma16816(float* d, const uint32_t* a,
                                         uint32_t b0, uint32_t b1) {
    asm volatile(
        "mma.sync.aligned.m16n8k16.row.col.f32.f16.f16.f32 "
        "{%0,%1,%2,%3}, {%4,%5,%6,%7}, {%8,%9}, {%0,%1,%2,%3};"
        : "+f"(d[0]), "+f"(d[1]), "+f"(d[2]), "+f"(d[3])
        : "r"(a[0]), "r"(a[1]), "r"(a[2]), "r"(a[3]), "r"(b0), "r"(b1));
}
__device__ __forceinline__ uint32_t pack_h2(fp16 a, fp16 b) {
    __half2 t(a, b);
    return *reinterpret_cast<uint32_t*>(&t);
}
__device__ __forceinline__ uint4 cvt8(const float* f) {
    return make_uint4(pack_h2(__float2half(f[0]), __float2half(f[1])),
                      pack_h2(__float2half(f[2]), __float2half(f[3])),
                      pack_h2(__float2half(f[4]), __float2half(f[5])),
                      pack_h2(__float2half(f[6]), __float2half(f[7])));
}
__device__ __forceinline__ float sigm(float x) { return 1.f / (1.f + expf(-x)); }

// ---------------- fused prep ----------------
#define T8_P1 (512 * 256 / 8)
#define T8_P2 (256 * 512 / 8)
#define T8_WI (2048 * 256 / 8)
#define T8_WH (2048 * 256 / 8)
#define T8_ALL (T8_P1 + T8_P2 + T8_WI + T8_WH)

__global__ void prep_all_kernel(const float* __restrict__ gcnW,
                                const float* __restrict__ wb,
                                const float* __restrict__ gb,
                                const float* __restrict__ bih,
                                const float* __restrict__ bhh,
                                const int* __restrict__ qlc_i32,
                                const float* __restrict__ p1W,
                                const float* __restrict__ p2W,
                                const float* __restrict__ Wih,
                                const float* __restrict__ Whh) {
    int idx = blockIdx.x * blockDim.x + threadIdx.x;
    if (idx == 0) {
        int any = 0;
        for (int i = 1; i < 2 * NB; i += 2) any |= qlc_i32[i];
        g_is64 = (any == 0) ? 1 : 0;
    }
    if (idx < 256 * 128) {
        int j = idx >> 7, e = idx & 127;
        float v = (j < 128) ? gcnW[j * 256 + e] : gcnW[(j - 128) * 256 + 128 + e];
        g_Wph[idx] = __float2half(v);
    }
    if (idx < 256) g_biasproj[idx] = (idx < 128) ? (wb[idx] + gb[idx]) : 0.f;
    if (idx < G4)  g_bsum[idx] = bih[idx] + bhh[idx];

    if (idx < T8_ALL) {
        const float* src;
        fp16* dst;
        int e0;
        if (idx < T8_P1) {
            e0 = idx * 8; src = p1W + e0; dst = g_p1h + e0;
        } else if (idx < T8_P1 + T8_P2) {
            e0 = (idx - T8_P1) * 8; src = p2W + e0; dst = g_p2h + e0;
        } else if (idx < T8_P1 + T8_P2 + T8_WI) {
            e0 = (idx - T8_P1 - T8_P2) * 8; src = Wih + e0; dst = g_Wihh + e0;
        } else {
            e0 = (idx - T8_P1 - T8_P2 - T8_WI) * 8;
            int row = e0 >> 8, col = e0 & 255;
            src = Whh + (size_t)row * 512 + col;
            dst = g_Whhh + e0;
        }
        float4 v0 = *reinterpret_cast<const float4*>(src);
        float4 v1 = *reinterpret_cast<const float4*>(src + 4);
        float f[8] = {v0.x, v0.y, v0.z, v0.w, v1.x, v1.y, v1.z, v1.w};
        *reinterpret_cast<uint4*>(dst) = cvt8(f);
    }
}

// =====================================================================
// proj_mma: g_projh[NSYM,256] = fp16(emb @ Wproj^T + bias)
// =====================================================================
#define ROWB 272
#define PA_OFF 0
#define PB_OFF (128 * ROWB)
#define PROJ_SMEM (PB_OFF + 256 * ROWB)   // 104448

__global__ void __launch_bounds__(256, 2)
proj_mma_kernel(const float* __restrict__ emb) {
    extern __shared__ char sm[];
    const uint32_t sbase = smem_u32(sm);
    const int tid = threadIdx.x;
    const int mbase = blockIdx.x * 128;

#pragma unroll
    for (int i = 0; i < 8; ++i) {
        int c = tid + i * 256;
        int row = c >> 4, ch = c & 15;
        int grow = mbase + row;
        uint4 h = make_uint4(0, 0, 0, 0);
        if (grow < NSYM) {
            const float* p = emb + (size_t)grow * 128 + ch * 8;
            float4 v0 = *reinterpret_cast<const float4*>(p);
            float4 v1 = *reinterpret_cast<const float4*>(p + 4);
            float f[8] = {v0.x, v0.y, v0.z, v0.w, v1.x, v1.y, v1.z, v1.w};
            h = cvt8(f);
        }
        *reinterpret_cast<uint4*>(sm + PA_OFF + row * ROWB + ch * 16) = h;
    }
#pragma unroll
    for (int i = 0; i < 16; ++i) {
        int c = tid + i * 256;
        int row = c >> 4, ch = c & 15;
        uint4 h = *reinterpret_cast<const uint4*>(g_Wph + row * 128 + ch * 8);
        *reinterpret_cast<uint4*>(sm + PB_OFF + row * ROWB + ch * 16) = h;
    }
    __syncthreads();

    const int warp = tid >> 5, lane = tid & 31;
    const int wm = warp & 3, wn = warp >> 2;
    const int m0 = wm * 32, n0 = wn * 64;

    const int a_row = (lane & 15);
    const int a_kadd = (lane >> 4) << 3;
    const int b_row = ((lane >> 4) << 3) + (lane & 7);
    const int b_kadd = ((lane >> 3) & 1) << 3;

    for (int half = 0; half < 2; ++half) {
        const uint32_t bofs = PB_OFF + half * 128 * ROWB;

        float acc[2][8][4];
#pragma unroll
        for (int i = 0; i < 2; ++i)
#pragma unroll
            for (int j = 0; j < 8; ++j)
#pragma unroll
                for (int q = 0; q < 4; ++q) acc[i][j][q] = 0.f;

#pragma unroll
        for (int ks = 0; ks < 8; ++ks) {
            const int k0 = ks * 16;
            uint32_t ra[2][4];
#pragma unroll
            for (int mi = 0; mi < 2; ++mi)
                ldmatrix4(sbase + PA_OFF + (m0 + mi * 16 + a_row) * ROWB + (k0 + a_kadd) * 2,
                          ra[mi][0], ra[mi][1], ra[mi][2], ra[mi][3]);
            uint32_t rb[4][4];
#pragma unroll
            for (int np = 0; np < 4; ++np)
                ldmatrix4(sbase + bofs + (n0 + np * 16 + b_row) * ROWB + (k0 + b_kadd) * 2,
                          rb[np][0], rb[np][1], rb[np][2], rb[np][3]);
#pragma unroll
            for (int mi = 0; mi < 2; ++mi)
#pragma unroll
                for (int ni = 0; ni < 8; ++ni)
                    mma16816(acc[mi][ni], ra[mi],
                             rb[ni >> 1][(ni & 1) * 2 + 0], rb[ni >> 1][(ni & 1) * 2 + 1]);
        }

        const int rbase = mbase + m0;
#pragma unroll
        for (int mi = 0; mi < 2; ++mi) {
#pragma unroll
            for (int ni = 0; ni < 8; ++ni) {
                int gcol = half * 128 + n0 + ni * 8 + (lane & 3) * 2;
                float b0 = g_biasproj[gcol], b1 = g_biasproj[gcol + 1];
                int r0 = rbase + mi * 16 + (lane >> 2);
                int r1 = r0 + 8;
                if (r0 < NSYM)
                    *reinterpret_cast<uint32_t*>(g_projh + (size_t)r0 * 256 + gcol) =
                        pack_h2(__float2half(acc[mi][ni][0] + b0),
                                __float2half(acc[mi][ni][1] + b1));
                if (r1 < NSYM)
                    *reinterpret_cast<uint32_t*>(g_projh + (size_t)r1 * 256 + gcol) =
                        pack_h2(__float2half(acc[mi][ni][2] + b0),
                                __float2half(acc[mi][ni][3] + b1));
            }
        }
    }
}

// =====================================================================
// hgemm_small: 64(M) x 128(N) tile, 128 threads (2Mx2N warps of 32x64)
// colSel: 0 = ntile = blockIdx.x*128 (normal)
//         1 = step-4 column subset: tiles {0,1,4,5,8,9,12,13}
// =====================================================================
#define KROWB 144
#define HS_A  0
#define HS_B  (64 * KROWB)
#define HS_SMEM ((64 + 128) * KROWB)   // 27648

__global__ void __launch_bounds__(128, 4)
hgemm_small(int M, int N, int K,
            const fp16* __restrict__ A, const fp16* __restrict__ B,
            const float* __restrict__ bias, const float* __restrict__ addMat,
            float* __restrict__ C, fp16* __restrict__ Chi, int doRelu, int colSel) {
    extern __shared__ char sm[];
    const uint32_t sbase = smem_u32(sm);
    const int tid = threadIdx.x;
    const int mtile = blockIdx.y * 64;
    int bx = blockIdx.x;
    if (colSel) bx = (bx & 1) + ((bx >> 1) << 2);   // {0,1,4,5,8,9,12,13}
    const int ntile = bx * 128;

    const int warp = tid >> 5, lane = tid & 31;
    const int wm = warp & 1, wn = warp >> 1;
    const int m0 = wm * 32, n0 = wn * 64;

    float acc[2][8][4];
#pragma unroll
    for (int i = 0; i < 2; ++i)
#pragma unroll
        for (int j = 0; j < 8; ++j)
#pragma unroll
            for (int q = 0; q < 4; ++q) acc[i][j][q] = 0.f;

    const int a_row = (lane & 15);
    const int a_kadd = (lane >> 4) << 3;
    const int b_row = ((lane >> 4) << 3) + (lane & 7);
    const int b_kadd = ((lane >> 3) & 1) << 3;

    for (int kc = 0; kc < K; kc += 64) {
#pragma unroll
        for (int i = 0; i < 4; ++i) {
            int c = tid + i * 128;
            int row = c >> 3, ch = c & 7;
            int grow = mtile + row;
            uint4 h = make_uint4(0, 0, 0, 0);
            if (grow < M)
                h = *reinterpret_cast<const uint4*>(A + (size_t)grow * K + kc + ch * 8);
            *reinterpret_cast<uint4*>(sm + HS_A + row * KROWB + ch * 16) = h;
        }
#pragma unroll
        for (int i = 0; i < 8; ++i) {
            int c = tid + i * 128;
            int row = c >> 3, ch = c & 7;
            int grow = ntile + row;
            uint4 h = *reinterpret_cast<const uint4*>(B + (size_t)grow * K + kc + ch * 8);
            *reinterpret_cast<uint4*>(sm + HS_B + row * KROWB + ch * 16) = h;
        }
        __syncthreads();

#pragma unroll
        for (int ks = 0; ks < 4; ++ks) {
            const int k0 = ks * 16;
            uint32_t ra[2][4];
#pragma unroll
            for (int mi = 0; mi < 2; ++mi)
                ldmatrix4(sbase + HS_A + (m0 + mi * 16 + a_row) * KROWB + (k0 + a_kadd) * 2,
                          ra[mi][0], ra[mi][1], ra[mi][2], ra[mi][3]);
            uint32_t rb[4][4];
#pragma unroll
            for (int np = 0; np < 4; ++np)
                ldmatrix4(sbase + HS_B + (n0 + np * 16 + b_row) * KROWB + (k0 + b_kadd) * 2,
                          rb[np][0], rb[np][1], rb[np][2], rb[np][3]);
#pragma unroll
            for (int mi = 0; mi < 2; ++mi)
#pragma unroll
                for (int ni = 0; ni < 8; ++ni)
                    mma16816(acc[mi][ni], ra[mi],
                             rb[ni >> 1][(ni & 1) * 2 + 0], rb[ni >> 1][(ni & 1) * 2 + 1]);
        }
        __syncthreads();
    }

#pragma unroll
    for (int mi = 0; mi < 2; ++mi) {
#pragma unroll
        for (int ni = 0; ni < 8; ++ni) {
            int col = ntile + n0 + ni * 8 + (lane & 3) * 2;
            float b0 = bias ? bias[col] : 0.f;
            float b1 = bias ? bias[col + 1] : 0.f;
#pragma unroll
            for (int half = 0; half < 2; ++half) {
                int r = mtile + m0 + mi * 16 + (lane >> 2) + half * 8;
                if (r >= M) continue;
                float vx = acc[mi][ni][half * 2 + 0] + b0;
                float vy = acc[mi][ni][half * 2 + 1] + b1;
                if (addMat) {
                    vx += addMat[(size_t)r * N + col];
                    vy += addMat[(size_t)r * N + col + 1];
                }
                if (doRelu) { vx = fmaxf(vx, 0.f); vy = fmaxf(vy, 0.f); }
                if (C)
                    *reinterpret_cast<float2*>(C + (size_t)r * N + col) = make_float2(vx, vy);
                if (Chi)
                    *reinterpret_cast<uint32_t*>(Chi + (size_t)r * N + col) =
                        pack_h2(__float2half(vx), __float2half(vy));
            }
        }
    }
}

// ---------------- neighbor encoder: half2 full-line gather, split-k ----
__global__ void __launch_bounds__(128)
neighbor_kernel(const void* qlc, const void* qrc, const void* slc, const void* src) {
    __shared__ int sidx[2 * NB];
    __shared__ float redA[128];
    int b = blockIdx.x;
    const void* conn;
    int node, off;
    if (b < BQ)                { conn = qlc; node = b;                off = node * DM; }
    else if (b < 2 * BQ)       { conn = qrc; node = b - BQ;           off = node * DM + 128; }
    else if (b < 2 * BQ + FEW) { conn = slc; node = b - 2 * BQ;       off = (BQ + node) * DM; }
    else                       { conn = src; node = b - 2 * BQ - FEW; off = (BQ + node) * DM + 128; }

    int tid = threadIdx.x;
    size_t base = (size_t)node * (2 * NB);
    if (g_is64) {
        const long long* p = (const long long*)conn;
        for (int t = tid; t < 2 * NB; t += 128) sidx[t] = (int)p[base + t];
    } else {
        const int* p = (const int*)conn;
        for (int t = tid; t < 2 * NB; t += 128) sidx[t] = p[base + t];
    }
    __syncthreads();

    const fp16* __restrict__ proj = g_projh;
    const int grp = tid >> 6;
    const int c2 = (tid & 63) * 2;

    float m0 = -INFINITY, m1 = -INFINITY;
    for (int k = grp; k < NB; k += 2) {
        int rel = sidx[2 * k], ent = sidx[2 * k + 1];
        if (rel == PADID || ent == PADID) continue;
        __half2 a = *reinterpret_cast<const __half2*>(proj + (size_t)rel * 256 + c2);
        __half2 e = *reinterpret_cast<const __half2*>(proj + (size_t)ent * 256 + 128 + c2);
        float v0 = __half2float(__low2half(a)) + __half2float(__low2half(e));
        float v1 = __half2float(__high2half(a)) + __half2float(__high2half(e));
        v0 = (v0 > 0.f) ? v0 : 0.1f * v0;
        v1 = (v1 > 0.f) ? v1 : 0.1f * v1;
        m0 = fmaxf(m0, v0);
        m1 = fmaxf(m1, v1);
    }

    if (grp == 0) { redA[c2] = m0; redA[c2 + 1] = m1; }
    __syncthreads();
    if (grp == 1) {
        float f0 = tanhf(fmaxf(m0, redA[c2]));
        float f1 = tanhf(fmaxf(m1, redA[c2 + 1]));
        *reinterpret_cast<float2*>(g_xcat + off + c2) = make_float2(f0, f1);
        *reinterpret_cast<uint32_t*>(g_xcath + off + c2) =
            pack_h2(__float2half(f0), __float2half(f1));
    }
}

// ---------------- layernorm ----------------
__global__ void ln_kernel(const float* __restrict__ lg, const float* __restrict__ lb) {
    __shared__ float red[256];
    int row = blockIdx.x, t = threadIdx.x;
    float v = g_oenc[row * DM + t];
    red[t] = v;
    __syncthreads();
    for (int s = 128; s > 0; s >>= 1) { if (t < s) red[t] += red[t + s]; __syncthreads(); }
    float mu = red[0] * (1.f / 256.f);
    __syncthreads();
    float d = v - mu;
    red[t] = d * d;
    __syncthreads();
    for (int s = 128; s > 0; s >>= 1) { if (t < s) red[t] += red[t + s]; __syncthreads(); }
    float var = red[0] * (1.f / 256.f);
    float o = d * rsqrtf(var + 1e-5f) * lg[t] + lb[t];
    g_enc[row * DM + t] = o;
    g_ench[row * DM + t] = __float2half(o);
}

// ---------------- fused mean + sconst ----------------
__global__ void sconst2_kernel(const float* __restrict__ Whh) {
    __shared__ float sup[256];
    int t = threadIdx.x;
    float s = 0.f;
    for (int r = 0; r < FEW; ++r) s += g_enc[(BQ + r) * DM + t];
    s *= (1.f / FEW);
    sup[t] = s;
    if (blockIdx.x == 0) g_support[t] = s;
    __syncthreads();

    int warp = t >> 5, lane = t & 31;
#pragma unroll
    for (int gi = 0; gi < 4; ++gi) {
        int gidx = blockIdx.x * 32 + warp * 4 + gi;
        float acc = 0.f;
        for (int i = lane; i < DM; i += 32)
            acc += sup[i] * Whh[(size_t)gidx * 512 + 256 + i];
#pragma unroll
        for (int o = 16; o > 0; o >>= 1) acc += __shfl_down_sync(0xffffffffu, acc, o);
        if (lane == 0) g_sconst[gidx] = acc;
    }
}

// ---------------- LSTM elementwise step (steps 1..3) ----------------
__global__ void lstm_kernel(const float* __restrict__ G, int firstStep) {
    int idx = blockIdx.x * blockDim.x + threadIdx.x;
    if (idx >= BQ * HID) return;
    int n = idx >> 9, j = idx & 511;
    const float* g = G + (size_t)n * G4;
    float gi = g[j], gf = g[512 + j], gg = g[1024 + j], go = g[1536 + j];
    float c  = firstStep ? 0.f : g_c[idx];
    float cn = sigm(gf) * c + sigm(gi) * tanhf(gg);
    g_c[idx] = cn;
    if (j < DM) {
        float hv = g_enc[n * DM + j] + sigm(go) * tanhf(cn);
        g_hh[n * DM + j] = __float2half(hv);
    }
}

// ---------------- last LSTM step fused with final dot ----------------
__global__ void lstm_last_kernel(const float* __restrict__ G, float* __restrict__ out) {
    __shared__ float red[256];
    int n = blockIdx.x, j = threadIdx.x;
    const float* g = G + (size_t)n * G4;
    float gi = g[j], gf = g[512 + j], gg = g[1024 + j], go = g[1536 + j];
    float c  = g_c[n * 512 + j];
    float cn = sigm(gf) * c + sigm(gi) * tanhf(gg);
    float hv = g_enc[n * DM + j] + sigm(go) * tanhf(cn);
    red[j] = hv * g_support[j];
    __syncthreads();
    for (int s = 128; s > 0; s >>= 1) { if (j < s) red[j] += red[j + s]; __syncthreads(); }
    if (j == 0) out[n] = red[0];
}

// ---------------- launch ----------------
extern "C" void kernel_launch(void* const* d_in, const int* in_sizes, int n_in,
                              void* d_out, int out_size) {
    const void* qlc = d_in[0];
    const void* qrc = d_in[1];
    const void* slc = d_in[2];
    const void* src = d_in[3];
    const float* emb  = (const float*)d_in[8];
    const float* gcnW = (const float*)d_in[9];
    const float* wb   = (const float*)d_in[10];
    const float* gb   = (const float*)d_in[11];
    const float* p1W  = (const float*)d_in[12];
    const float* p1b  = (const float*)d_in[13];
    const float* p2W  = (const float*)d_in[14];
    const float* p2b  = (const float*)d_in[15];
    const float* lng  = (const float*)d_in[16];
    const float* lnb  = (const float*)d_in[17];
    const float* Wih  = (const float*)d_in[18];
    const float* Whh  = (const float*)d_in[19];
    const float* bih  = (const float*)d_in[20];
    const float* bhh  = (const float*)d_in[21];

    fp16 *p1h, *p2h, *Wihh, *Whhh, *xcath, *hench, *ench, *hh;
    float *xcat, *oenc, *sconst, *qWihb, *gates, *bsum;
    cudaGetSymbolAddress((void**)&p1h,    g_p1h);
    cudaGetSymbolAddress((void**)&p2h,    g_p2h);
    cudaGetSymbolAddress((void**)&Wihh,   g_Wihh);
    cudaGetSymbolAddress((void**)&Whhh,   g_Whhh);
    cudaGetSymbolAddress((void**)&xcath,  g_xcath);
    cudaGetSymbolAddress((void**)&hench,  g_hench);
    cudaGetSymbolAddress((void**)&ench,   g_ench);
    cudaGetSymbolAddress((void**)&hh,     g_hh);
    cudaGetSymbolAddress((void**)&xcat,   g_xcat);
    cudaGetSymbolAddress((void**)&oenc,   g_oenc);
    cudaGetSymbolAddress((void**)&sconst, g_sconst);
    cudaGetSymbolAddress((void**)&qWihb,  g_qWihb);
    cudaGetSymbolAddress((void**)&gates,  g_gates);
    cudaGetSymbolAddress((void**)&bsum,   g_bsum);

    prep_all_kernel<<<(T8_ALL + 255) / 256, 256>>>(
        gcnW, wb, gb, bih, bhh, (const int*)qlc, p1W, p2W, Wih, Whh);

    cudaFuncSetAttribute(proj_mma_kernel,
                         cudaFuncAttributeMaxDynamicSharedMemorySize, PROJ_SMEM);
    proj_mma_kernel<<<(NSYM + 127) / 128, 256, PROJ_SMEM>>>(emb);

    neighbor_kernel<<<2 * BQ + 2 * FEW, 128>>>(qlc, qrc, slc, src);

    cudaFuncSetAttribute(hgemm_small,
                         cudaFuncAttributeMaxDynamicSharedMemorySize, HS_SMEM);

    // support encoder
    hgemm_small<<<dim3(512 / 128, (NROWS + 63) / 64), 128, HS_SMEM>>>(
        NROWS, 512, 256, xcath, p1h, p1b, nullptr, nullptr, hench, 1, 0);
    hgemm_small<<<dim3(256 / 128, (NROWS + 63) / 64), 128, HS_SMEM>>>(
        NROWS, 256, 512, hench, p2h, p2b, xcat, oenc, nullptr, 0, 0);
    ln_kernel<<<NROWS, 256>>>(lng, lnb);

    sconst2_kernel<<<G4 / 32, 256>>>(Whh);

    // qWihb = enc@Wih^T + (b_ih + b_hh)
    hgemm_small<<<dim3(G4 / 128, BQ / 64), 128, HS_SMEM>>>(
        BQ, G4, 256, ench, Wihh, bsum, nullptr, qWihb, nullptr, 0, 0);

    lstm_kernel<<<(BQ * HID + 255) / 256, 256>>>(qWihb, 1);

    for (int s = 1; s < 3; ++s) {
        hgemm_small<<<dim3(G4 / 128, BQ / 64), 128, HS_SMEM>>>(
            BQ, G4, 256, hh, Whhh, sconst, qWihb, gates, nullptr, 0, 0);
        lstm_kernel<<<(BQ * HID + 255) / 256, 256>>>(gates, 0);
    }
    // step-4 gates: only the 8 N-tiles consumed by lstm_last (j < 256 gates)
    hgemm_small<<<dim3(8, BQ / 64), 128, HS_SMEM>>>(
        BQ, G4, 256, hh, Whhh, sconst, qWihb, gates, nullptr, 0, 1);
    lstm_last_kernel<<<BQ, 256>>>(gates, (float*)d_out);
}

// round 14
// speedup vs baseline: 1.3239x; 1.1012x over previous
#include <cuda_runtime.h>
#include <cuda_fp16.h>
#include <cstdint>
#include <math.h>

// ---------------- problem constants ----------------
#define NSYM   200001
#define PADID  200000
#define BQ     1024
#define FEW    5
#define NB     200
#define DM     256
#define DI     512
#define HID    512
#define G4     2048
#define NROWS  (BQ + FEW)

typedef __half fp16;

// ---------------- device scratch ----------------
__device__ fp16  g_projh[(size_t)NSYM * 256];
__device__ fp16  g_Wph[256 * 128];
__device__ fp16  g_p1h[512 * 256];
__device__ fp16  g_p2h[256 * 512];
__device__ fp16  g_Wihh[2048 * 256];
__device__ fp16  g_Whhh[2048 * 256];
__device__ float g_biasproj[256];
__device__ float g_bsum[G4];
__device__ float g_xcat[NROWS * DM];
__device__ fp16  g_xcath[NROWS * DM];
__device__ fp16  g_hench[NROWS * DI];
__device__ float g_oenc[NROWS * DM];
__device__ float g_enc[NROWS * DM];
__device__ fp16  g_ench[NROWS * DM];
__device__ float g_support[DM];
__device__ float g_sconst[G4];
__device__ float g_qWihb[BQ * G4];
__device__ float g_gates[BQ * G4];
__device__ fp16  g_hh[BQ * DM];
__device__ float g_c[BQ * HID];
__device__ int   g_is64;

// ---------------- helpers ----------------
__device__ __forceinline__ uint32_t smem_u32(const void* p) {
    uint32_t a;
    asm("{ .reg .u64 t; cvta.to.shared.u64 t, %1; cvt.u32.u64 %0, t; }" : "=r"(a) : "l"(p));
    return a;
}
__device__ __forceinline__ void ldmatrix4(uint32_t addr, uint32_t& r0, uint32_t& r1,
                                          uint32_t& r2, uint32_t& r3) {
    asm volatile("ldmatrix.sync.aligned.m8n8.x4.shared.b16 {%0,%1,%2,%3}, [%4];"
                 : "=r"(r0), "=r"(r1), "=r"(r2), "=r"(r3) : "r"(addr));
}
__device__ __forceinline__ void mma16816(float* d, const uint32_t* a,
                                         uint32_t b0, uint32_t b1) {
    asm volatile(
        "mma.sync.aligned.m16n8k16.row.col.f32.f16.f16.f32 "
        "{%0,%1,%2,%3}, {%4,%5,%6,%7}, {%8,%9}, {%0,%1,%2,%3};"
        : "+f"(d[0]), "+f"(d[1]), "+f"(d[2]), "+f"(d[3])
        : "r"(a[0]), "r"(a[1]), "r"(a[2]), "r"(a[3]), "r"(b0), "r"(b1));
}
__device__ __forceinline__ uint32_t pack_h2(fp16 a, fp16 b) {
    __half2 t(a, b);
    return *reinterpret_cast<uint32_t*>(&t);
}
__device__ __forceinline__ uint4 cvt8(const float* f) {
    return make_uint4(pack_h2(__float2half(f[0]), __float2half(f[1])),
                      pack_h2(__float2half(f[2]), __float2half(f[3])),
                      pack_h2(__float2half(f[4]), __float2half(f[5])),
                      pack_h2(__float2half(f[6]), __float2half(f[7])));
}
__device__ __forceinline__ float sigm(float x) { return 1.f / (1.f + expf(-x)); }

// cp.async 16B with zero-fill predicate (src-size = 0 zero-fills)
__device__ __forceinline__ void cp_async16(uint32_t dst, const void* src, int pred) {
    int sz = pred ? 16 : 0;
    asm volatile("cp.async.ca.shared.global [%0], [%1], 16, %2;"
                 :: "r"(dst), "l"(src), "r"(sz));
}
__device__ __forceinline__ void cp_commit() {
    asm volatile("cp.async.commit_group;" ::: "memory");
}
__device__ __forceinline__ void cp_wait0() {
    asm volatile("cp.async.wait_group 0;" ::: "memory");
}

// ---------------- fused prep ----------------
#define T8_P1 (512 * 256 / 8)
#define T8_P2 (256 * 512 / 8)
#define T8_WI (2048 * 256 / 8)
#define T8_WH (2048 * 256 / 8)
#define T8_ALL (T8_P1 + T8_P2 + T8_WI + T8_WH)

__global__ void prep_all_kernel(const float* __restrict__ gcnW,
                                const float* __restrict__ wb,
                                const float* __restrict__ gb,
                                const float* __restrict__ bih,
                                const float* __restrict__ bhh,
                                const int* __restrict__ qlc_i32,
                                const float* __restrict__ p1W,
                                const float* __restrict__ p2W,
                                const float* __restrict__ Wih,
                                const float* __restrict__ Whh) {
    int idx = blockIdx.x * blockDim.x + threadIdx.x;
    if (idx == 0) {
        int any = 0;
        for (int i = 1; i < 2 * NB; i += 2) any |= qlc_i32[i];
        g_is64 = (any == 0) ? 1 : 0;
    }
    if (idx < 256 * 128) {
        int j = idx >> 7, e = idx & 127;
        float v = (j < 128) ? gcnW[j * 256 + e] : gcnW[(j - 128) * 256 + 128 + e];
        g_Wph[idx] = __float2half(v);
    }
    if (idx < 256) g_biasproj[idx] = (idx < 128) ? (wb[idx] + gb[idx]) : 0.f;
    if (idx < G4)  g_bsum[idx] = bih[idx] + bhh[idx];

    if (idx < T8_ALL) {
        const float* src;
        fp16* dst;
        int e0;
        if (idx < T8_P1) {
            e0 = idx * 8; src = p1W + e0; dst = g_p1h + e0;
        } else if (idx < T8_P1 + T8_P2) {
            e0 = (idx - T8_P1) * 8; src = p2W + e0; dst = g_p2h + e0;
        } else if (idx < T8_P1 + T8_P2 + T8_WI) {
            e0 = (idx - T8_P1 - T8_P2) * 8; src = Wih + e0; dst = g_Wihh + e0;
        } else {
            e0 = (idx - T8_P1 - T8_P2 - T8_WI) * 8;
            int row = e0 >> 8, col = e0 & 255;
            src = Whh + (size_t)row * 512 + col;
            dst = g_Whhh + e0;
        }
        float4 v0 = *reinterpret_cast<const float4*>(src);
        float4 v1 = *reinterpret_cast<const float4*>(src + 4);
        float f[8] = {v0.x, v0.y, v0.z, v0.w, v1.x, v1.y, v1.z, v1.w};
        *reinterpret_cast<uint4*>(dst) = cvt8(f);
    }
}

// =====================================================================
// proj_mma: g_projh[NSYM,256] = fp16(emb @ Wproj^T + bias)
// =====================================================================
#define ROWB 272
#define PA_OFF 0
#define PB_OFF (128 * ROWB)
#define PROJ_SMEM (PB_OFF + 256 * ROWB)   // 104448

__global__ void __launch_bounds__(256, 2)
proj_mma_kernel(const float* __restrict__ emb) {
    extern __shared__ char sm[];
    const uint32_t sbase = smem_u32(sm);
    const int tid = threadIdx.x;
    const int mbase = blockIdx.x * 128;

#pragma unroll
    for (int i = 0; i < 8; ++i) {
        int c = tid + i * 256;
        int row = c >> 4, ch = c & 15;
        int grow = mbase + row;
        uint4 h = make_uint4(0, 0, 0, 0);
        if (grow < NSYM) {
            const float* p = emb + (size_t)grow * 128 + ch * 8;
            float4 v0 = *reinterpret_cast<const float4*>(p);
            float4 v1 = *reinterpret_cast<const float4*>(p + 4);
            float f[8] = {v0.x, v0.y, v0.z, v0.w, v1.x, v1.y, v1.z, v1.w};
            h = cvt8(f);
        }
        *reinterpret_cast<uint4*>(sm + PA_OFF + row * ROWB + ch * 16) = h;
    }
#pragma unroll
    for (int i = 0; i < 16; ++i) {
        int c = tid + i * 256;
        int row = c >> 4, ch = c & 15;
        uint4 h = *reinterpret_cast<const uint4*>(g_Wph + row * 128 + ch * 8);
        *reinterpret_cast<uint4*>(sm + PB_OFF + row * ROWB + ch * 16) = h;
    }
    __syncthreads();

    const int warp = tid >> 5, lane = tid & 31;
    const int wm = warp & 3, wn = warp >> 2;
    const int m0 = wm * 32, n0 = wn * 64;

    const int a_row = (lane & 15);
    const int a_kadd = (lane >> 4) << 3;
    const int b_row = ((lane >> 4) << 3) + (lane & 7);
    const int b_kadd = ((lane >> 3) & 1) << 3;

    for (int half = 0; half < 2; ++half) {
        const uint32_t bofs = PB_OFF + half * 128 * ROWB;

        float acc[2][8][4];
#pragma unroll
        for (int i = 0; i < 2; ++i)
#pragma unroll
            for (int j = 0; j < 8; ++j)
#pragma unroll
                for (int q = 0; q < 4; ++q) acc[i][j][q] = 0.f;

#pragma unroll
        for (int ks = 0; ks < 8; ++ks) {
            const int k0 = ks * 16;
            uint32_t ra[2][4];
#pragma unroll
            for (int mi = 0; mi < 2; ++mi)
                ldmatrix4(sbase + PA_OFF + (m0 + mi * 16 + a_row) * ROWB + (k0 + a_kadd) * 2,
                          ra[mi][0], ra[mi][1], ra[mi][2], ra[mi][3]);
            uint32_t rb[4][4];
#pragma unroll
            for (int np = 0; np < 4; ++np)
                ldmatrix4(sbase + bofs + (n0 + np * 16 + b_row) * ROWB + (k0 + b_kadd) * 2,
                          rb[np][0], rb[np][1], rb[np][2], rb[np][3]);
#pragma unroll
            for (int mi = 0; mi < 2; ++mi)
#pragma unroll
                for (int ni = 0; ni < 8; ++ni)
                    mma16816(acc[mi][ni], ra[mi],
                             rb[ni >> 1][(ni & 1) * 2 + 0], rb[ni >> 1][(ni & 1) * 2 + 1]);
        }

        const int rbase = mbase + m0;
#pragma unroll
        for (int mi = 0; mi < 2; ++mi) {
#pragma unroll
            for (int ni = 0; ni < 8; ++ni) {
                int gcol = half * 128 + n0 + ni * 8 + (lane & 3) * 2;
                float b0 = g_biasproj[gcol], b1 = g_biasproj[gcol + 1];
                int r0 = rbase + mi * 16 + (lane >> 2);
                int r1 = r0 + 8;
                if (r0 < NSYM)
                    *reinterpret_cast<uint32_t*>(g_projh + (size_t)r0 * 256 + gcol) =
                        pack_h2(__float2half(acc[mi][ni][0] + b0),
                                __float2half(acc[mi][ni][1] + b1));
                if (r1 < NSYM)
                    *reinterpret_cast<uint32_t*>(g_projh + (size_t)r1 * 256 + gcol) =
                        pack_h2(__float2half(acc[mi][ni][2] + b0),
                                __float2half(acc[mi][ni][3] + b1));
            }
        }
    }
}

// =====================================================================
// hgemm_small: 64(M) x 128(N) tile, 128 threads, cp.async double-buffered.
// colSel: 1 = step-4 column subset: tiles {0,1,4,5,8,9,12,13}
// =====================================================================
#define KROWB 144
#define HS_BUF ((64 + 128) * KROWB)    // one buffer: A(64 rows) + B(128 rows)
#define HS_A   0
#define HS_B   (64 * KROWB)
#define HS_SMEM (2 * HS_BUF)           // 55296

__global__ void __launch_bounds__(128, 4)
hgemm_small(int M, int N, int K,
            const fp16* __restrict__ A, const fp16* __restrict__ B,
            const float* __restrict__ bias, const float* __restrict__ addMat,
            float* __restrict__ C, fp16* __restrict__ Chi, int doRelu, int colSel) {
    extern __shared__ char sm[];
    const uint32_t sbase = smem_u32(sm);
    const int tid = threadIdx.x;
    const int mtile = blockIdx.y * 64;
    int bx = blockIdx.x;
    if (colSel) bx = (bx & 1) + ((bx >> 1) << 2);
    const int ntile = bx * 128;

    const int warp = tid >> 5, lane = tid & 31;
    const int wm = warp & 1, wn = warp >> 1;
    const int m0 = wm * 32, n0 = wn * 64;

    float acc[2][8][4];
#pragma unroll
    for (int i = 0; i < 2; ++i)
#pragma unroll
        for (int j = 0; j < 8; ++j)
#pragma unroll
            for (int q = 0; q < 4; ++q) acc[i][j][q] = 0.f;

    const int a_row = (lane & 15);
    const int a_kadd = (lane >> 4) << 3;
    const int b_row = ((lane >> 4) << 3) + (lane & 7);
    const int b_kadd = ((lane >> 3) & 1) << 3;

    // per-thread copy assignments (fixed across chunks)
    //   A: 4 chunks of 16B; B: 8 chunks of 16B
    const int a_r0 = tid >> 1;               // with i*... see loop below
    (void)a_r0;

    // issue cp.async for chunk at kc into buffer buf
    auto issue_chunk = [&](int kc, int buf) {
        uint32_t dst0 = sbase + buf * HS_BUF;
#pragma unroll
        for (int i = 0; i < 4; ++i) {
            int c = tid + i * 128;
            int row = c >> 3, ch = c & 7;
            int grow = mtile + row;
            int ok = grow < M;
            const fp16* src = A + (size_t)(ok ? grow : 0) * K + kc + ch * 8;
            cp_async16(dst0 + HS_A + row * KROWB + ch * 16, src, ok);
        }
#pragma unroll
        for (int i = 0; i < 8; ++i) {
            int c = tid + i * 128;
            int row = c >> 3, ch = c & 7;
            int grow = ntile + row;   // N multiple of 128
            const fp16* src = B + (size_t)grow * K + kc + ch * 8;
            cp_async16(dst0 + HS_B + row * KROWB + ch * 16, src, 1);
        }
        cp_commit();
    };

    int buf = 0;
    issue_chunk(0, 0);
    cp_wait0();
    __syncthreads();

    for (int kc = 0; kc < K; kc += 64) {
        int has_next = (kc + 64 < K);
        if (has_next) issue_chunk(kc + 64, buf ^ 1);

        const uint32_t cb = sbase + buf * HS_BUF;
#pragma unroll
        for (int ks = 0; ks < 4; ++ks) {
            const int k0 = ks * 16;
            uint32_t ra[2][4];
#pragma unroll
            for (int mi = 0; mi < 2; ++mi)
                ldmatrix4(cb + HS_A + (m0 + mi * 16 + a_row) * KROWB + (k0 + a_kadd) * 2,
                          ra[mi][0], ra[mi][1], ra[mi][2], ra[mi][3]);
            uint32_t rb[4][4];
#pragma unroll
            for (int np = 0; np < 4; ++np)
                ldmatrix4(cb + HS_B + (n0 + np * 16 + b_row) * KROWB + (k0 + b_kadd) * 2,
                          rb[np][0], rb[np][1], rb[np][2], rb[np][3]);
#pragma unroll
            for (int mi = 0; mi < 2; ++mi)
#pragma unroll
                for (int ni = 0; ni < 8; ++ni)
                    mma16816(acc[mi][ni], ra[mi],
                             rb[ni >> 1][(ni & 1) * 2 + 0], rb[ni >> 1][(ni & 1) * 2 + 1]);
        }
        if (has_next) {
            cp_wait0();
            __syncthreads();
            buf ^= 1;
        }
    }

#pragma unroll
    for (int mi = 0; mi < 2; ++mi) {
#pragma unroll
        for (int ni = 0; ni < 8; ++ni) {
            int col = ntile + n0 + ni * 8 + (lane & 3) * 2;
            float b0 = bias ? bias[col] : 0.f;
            float b1 = bias ? bias[col + 1] : 0.f;
#pragma unroll
            for (int half = 0; half < 2; ++half) {
                int r = mtile + m0 + mi * 16 + (lane >> 2) + half * 8;
                if (r >= M) continue;
                float vx = acc[mi][ni][half * 2 + 0] + b0;
                float vy = acc[mi][ni][half * 2 + 1] + b1;
                if (addMat) {
                    vx += addMat[(size_t)r * N + col];
                    vy += addMat[(size_t)r * N + col + 1];
                }
                if (doRelu) { vx = fmaxf(vx, 0.f); vy = fmaxf(vy, 0.f); }
                if (C)
                    *reinterpret_cast<float2*>(C + (size_t)r * N + col) = make_float2(vx, vy);
                if (Chi)
                    *reinterpret_cast<uint32_t*>(Chi + (size_t)r * N + col) =
                        pack_h2(__float2half(vx), __float2half(vy));
            }
        }
    }
}

// ---------------- neighbor encoder: half2 full-line gather, split-k ----
__global__ void __launch_bounds__(128)
neighbor_kernel(const void* qlc, const void* qrc, const void* slc, const void* src) {
    __shared__ int sidx[2 * NB];
    __shared__ float redA[128];
    int b = blockIdx.x;
    const void* conn;
    int node, off;
    if (b < BQ)                { conn = qlc; node = b;                off = node * DM; }
    else if (b < 2 * BQ)       { conn = qrc; node = b - BQ;           off = node * DM + 128; }
    else if (b < 2 * BQ + FEW) { conn = slc; node = b - 2 * BQ;       off = (BQ + node) * DM; }
    else                       { conn = src; node = b - 2 * BQ - FEW; off = (BQ + node) * DM + 128; }

    int tid = threadIdx.x;
    size_t base = (size_t)node * (2 * NB);
    if (g_is64) {
        const long long* p = (const long long*)conn;
        for (int t = tid; t < 2 * NB; t += 128) sidx[t] = (int)p[base + t];
    } else {
        const int* p = (const int*)conn;
        for (int t = tid; t < 2 * NB; t += 128) sidx[t] = p[base + t];
    }
    __syncthreads();

    const fp16* __restrict__ proj = g_projh;
    const int grp = tid >> 6;
    const int c2 = (tid & 63) * 2;

    float m0 = -INFINITY, m1 = -INFINITY;
    for (int k = grp; k < NB; k += 2) {
        int rel = sidx[2 * k], ent = sidx[2 * k + 1];
        if (rel == PADID || ent == PADID) continue;
        __half2 a = *reinterpret_cast<const __half2*>(proj + (size_t)rel * 256 + c2);
        __half2 e = *reinterpret_cast<const __half2*>(proj + (size_t)ent * 256 + 128 + c2);
        float v0 = __half2float(__low2half(a)) + __half2float(__low2half(e));
        float v1 = __half2float(__high2half(a)) + __half2float(__high2half(e));
        v0 = (v0 > 0.f) ? v0 : 0.1f * v0;
        v1 = (v1 > 0.f) ? v1 : 0.1f * v1;
        m0 = fmaxf(m0, v0);
        m1 = fmaxf(m1, v1);
    }

    if (grp == 0) { redA[c2] = m0; redA[c2 + 1] = m1; }
    __syncthreads();
    if (grp == 1) {
        float f0 = tanhf(fmaxf(m0, redA[c2]));
        float f1 = tanhf(fmaxf(m1, redA[c2 + 1]));
        *reinterpret_cast<float2*>(g_xcat + off + c2) = make_float2(f0, f1);
        *reinterpret_cast<uint32_t*>(g_xcath + off + c2) =
            pack_h2(__float2half(f0), __float2half(f1));
    }
}

// ---------------- layernorm ----------------
__global__ void ln_kernel(const float* __restrict__ lg, const float* __restrict__ lb) {
    __shared__ float red[256];
    int row = blockIdx.x, t = threadIdx.x;
    float v = g_oenc[row * DM + t];
    red[t] = v;
    __syncthreads();
    for (int s = 128; s > 0; s >>= 1) { if (t < s) red[t] += red[t + s]; __syncthreads(); }
    float mu = red[0] * (1.f / 256.f);
    __syncthreads();
    float d = v - mu;
    red[t] = d * d;
    __syncthreads();
    for (int s = 128; s > 0; s >>= 1) { if (t < s) red[t] += red[t + s]; __syncthreads(); }
    float var = red[0] * (1.f / 256.f);
    float o = d * rsqrtf(var + 1e-5f) * lg[t] + lb[t];
    g_enc[row * DM + t] = o;
    g_ench[row * DM + t] = __float2half(o);
}

// ---------------- fused mean + sconst ----------------
__global__ void sconst2_kernel(const float* __restrict__ Whh) {
    __shared__ float sup[256];
    int t = threadIdx.x;
    float s = 0.f;
    for (int r = 0; r < FEW; ++r) s += g_enc[(BQ + r) * DM + t];
    s *= (1.f / FEW);
    sup[t] = s;
    if (blockIdx.x == 0) g_support[t] = s;
    __syncthreads();

    int warp = t >> 5, lane = t & 31;
#pragma unroll
    for (int gi = 0; gi < 4; ++gi) {
        int gidx = blockIdx.x * 32 + warp * 4 + gi;
        float acc = 0.f;
        for (int i = lane; i < DM; i += 32)
            acc += sup[i] * Whh[(size_t)gidx * 512 + 256 + i];
#pragma unroll
        for (int o = 16; o > 0; o >>= 1) acc += __shfl_down_sync(0xffffffffu, acc, o);
        if (lane == 0) g_sconst[gidx] = acc;
    }
}

// ---------------- LSTM elementwise step (steps 1..3) ----------------
__global__ void lstm_kernel(const float* __restrict__ G, int firstStep) {
    int idx = blockIdx.x * blockDim.x + threadIdx.x;
    if (idx >= BQ * HID) return;
    int n = idx >> 9, j = idx & 511;
    const float* g = G + (size_t)n * G4;
    float gi = g[j], gf = g[512 + j], gg = g[1024 + j], go = g[1536 + j];
    float c  = firstStep ? 0.f : g_c[idx];
    float cn = sigm(gf) * c + sigm(gi) * tanhf(gg);
    g_c[idx] = cn;
    if (j < DM) {
        float hv = g_enc[n * DM + j] + sigm(go) * tanhf(cn);
        g_hh[n * DM + j] = __float2half(hv);
    }
}

// ---------------- last LSTM step fused with final dot ----------------
__global__ void lstm_last_kernel(const float* __restrict__ G, float* __restrict__ out) {
    __shared__ float red[256];
    int n = blockIdx.x, j = threadIdx.x;
    const float* g = G + (size_t)n * G4;
    float gi = g[j], gf = g[512 + j], gg = g[1024 + j], go = g[1536 + j];
    float c  = g_c[n * 512 + j];
    float cn = sigm(gf) * c + sigm(gi) * tanhf(gg);
    float hv = g_enc[n * DM + j] + sigm(go) * tanhf(cn);
    red[j] = hv * g_support[j];
    __syncthreads();
    for (int s = 128; s > 0; s >>= 1) { if (j < s) red[j] += red[j + s]; __syncthreads(); }
    if (j == 0) out[n] = red[0];
}

// ---------------- launch ----------------
extern "C" void kernel_launch(void* const* d_in, const int* in_sizes, int n_in,
                              void* d_out, int out_size) {
    const void* qlc = d_in[0];
    const void* qrc = d_in[1];
    const void* slc = d_in[2];
    const void* src = d_in[3];
    const float* emb  = (const float*)d_in[8];
    const float* gcnW = (const float*)d_in[9];
    const float* wb   = (const float*)d_in[10];
    const float* gb   = (const float*)d_in[11];
    const float* p1W  = (const float*)d_in[12];
    const float* p1b  = (const float*)d_in[13];
    const float* p2W  = (const float*)d_in[14];
    const float* p2b  = (const float*)d_in[15];
    const float* lng  = (const float*)d_in[16];
    const float* lnb  = (const float*)d_in[17];
    const float* Wih  = (const float*)d_in[18];
    const float* Whh  = (const float*)d_in[19];
    const float* bih  = (const float*)d_in[20];
    const float* bhh  = (const float*)d_in[21];

    fp16 *p1h, *p2h, *Wihh, *Whhh, *xcath, *hench, *ench, *hh;
    float *xcat, *oenc, *sconst, *qWihb, *gates, *bsum;
    cudaGetSymbolAddress((void**)&p1h,    g_p1h);
    cudaGetSymbolAddress((void**)&p2h,    g_p2h);
    cudaGetSymbolAddress((void**)&Wihh,   g_Wihh);
    cudaGetSymbolAddress((void**)&Whhh,   g_Whhh);
    cudaGetSymbolAddress((void**)&xcath,  g_xcath);
    cudaGetSymbolAddress((void**)&hench,  g_hench);
    cudaGetSymbolAddress((void**)&ench,   g_ench);
    cudaGetSymbolAddress((void**)&hh,     g_hh);
    cudaGetSymbolAddress((void**)&xcat,   g_xcat);
    cudaGetSymbolAddress((void**)&oenc,   g_oenc);
    cudaGetSymbolAddress((void**)&sconst, g_sconst);
    cudaGetSymbolAddress((void**)&qWihb,  g_qWihb);
    cudaGetSymbolAddress((void**)&gates,  g_gates);
    cudaGetSymbolAddress((void**)&bsum,   g_bsum);

    prep_all_kernel<<<(T8_ALL + 255) / 256, 256>>>(
        gcnW, wb, gb, bih, bhh, (const int*)qlc, p1W, p2W, Wih, Whh);

    cudaFuncSetAttribute(proj_mma_kernel,
                         cudaFuncAttributeMaxDynamicSharedMemorySize, PROJ_SMEM);
    proj_mma_kernel<<<(NSYM + 127) / 128, 256, PROJ_SMEM>>>(emb);

    neighbor_kernel<<<2 * BQ + 2 * FEW, 128>>>(qlc, qrc, slc, src);

    cudaFuncSetAttribute(hgemm_small,
                         cudaFuncAttributeMaxDynamicSharedMemorySize, HS_SMEM);

    // support encoder
    hgemm_small<<<dim3(512 / 128, (NROWS + 63) / 64), 128, HS_SMEM>>>(
        NROWS, 512, 256, xcath, p1h, p1b, nullptr, nullptr, hench, 1, 0);
    hgemm_small<<<dim3(256 / 128, (NROWS + 63) / 64), 128, HS_SMEM>>>(
        NROWS, 256, 512, hench, p2h, p2b, xcat, oenc, nullptr, 0, 0);
    ln_kernel<<<NROWS, 256>>>(lng, lnb);

    sconst2_kernel<<<G4 / 32, 256>>>(Whh);

    // qWihb = enc@Wih^T + (b_ih + b_hh)
    hgemm_small<<<dim3(G4 / 128, BQ / 64), 128, HS_SMEM>>>(
        BQ, G4, 256, ench, Wihh, bsum, nullptr, qWihb, nullptr, 0, 0);

    lstm_kernel<<<(BQ * HID + 255) / 256, 256>>>(qWihb, 1);

    for (int s = 1; s < 3; ++s) {
        hgemm_small<<<dim3(G4 / 128, BQ / 64), 128, HS_SMEM>>>(
            BQ, G4, 256, hh, Whhh, sconst, qWihb, gates, nullptr, 0, 0);
        lstm_kernel<<<(BQ * HID + 255) / 256, 256>>>(gates, 0);
    }
    // step-4 gates: only the 8 N-tiles consumed by lstm_last
    hgemm_small<<<dim3(8, BQ / 64), 128, HS_SMEM>>>(
        BQ, G4, 256, hh, Whhh, sconst, qWihb, gates, nullptr, 0, 1);
    lstm_last_kernel<<<BQ, 256>>>(gates, (float*)d_out);
}

// round 15
// speedup vs baseline: 1.3373x; 1.0101x over previous
#include <cuda_runtime.h>
#include <cuda_fp16.h>
#include <cstdint>
#include <math.h>

// ---------------- problem constants ----------------
#define NSYM   200001
#define PADID  200000
#define BQ     1024
#define FEW    5
#define NB     200
#define DM     256
#define DI     512
#define HID    512
#define G4     2048
#define NROWS  (BQ + FEW)

typedef __half fp16;

// ---------------- device scratch ----------------
__device__ fp16  g_projh[(size_t)NSYM * 256];
__device__ fp16  g_Wph[256 * 128];
__device__ fp16  g_p1h[512 * 256];
__device__ fp16  g_p2h[256 * 512];
__device__ fp16  g_Wihh[2048 * 256];
__device__ fp16  g_Whhh[2048 * 256];
__device__ float g_biasproj[256];
__device__ float g_bsum[G4];
__device__ float g_xcat[NROWS * DM];
__device__ fp16  g_xcath[NROWS * DM];
__device__ fp16  g_hench[NROWS * DI];
__device__ float g_oenc[NROWS * DM];
__device__ float g_enc[NROWS * DM];
__device__ fp16  g_ench[NROWS * DM];
__device__ float g_support[DM];
__device__ float g_sconst[G4];
__device__ float g_qWihb[BQ * G4];
__device__ float g_gates[BQ * G4];
__device__ fp16  g_hh[BQ * DM];
__device__ float g_c[BQ * HID];
__device__ int   g_is64;

// ---------------- helpers ----------------
__device__ __forceinline__ uint32_t smem_u32(const void* p) {
    uint32_t a;
    asm("{ .reg .u64 t; cvta.to.shared.u64 t, %1; cvt.u32.u64 %0, t; }" : "=r"(a) : "l"(p));
    return a;
}
__device__ __forceinline__ void ldmatrix4(uint32_t addr, uint32_t& r0, uint32_t& r1,
                                          uint32_t& r2, uint32_t& r3) {
    asm volatile("ldmatrix.sync.aligned.m8n8.x4.shared.b16 {%0,%1,%2,%3}, [%4];"
                 : "=r"(r0), "=r"(r1), "=r"(r2), "=r"(r3) : "r"(addr));
}
__device__ __forceinline__ void mma16816(float* d, const uint32_t* a,
                                         uint32_t b0, uint32_t b1) {
    asm volatile(
        "mma.sync.aligned.m16n8k16.row.col.f32.f16.f16.f32 "
        "{%0,%1,%2,%3}, {%4,%5,%6,%7}, {%8,%9}, {%0,%1,%2,%3};"
        : "+f"(d[0]), "+f"(d[1]), "+f"(d[2]), "+f"(d[3])
        : "r"(a[0]), "r"(a[1]), "r"(a[2]), "r"(a[3]), "r"(b0), "r"(b1));
}
__device__ __forceinline__ uint32_t pack_h2(fp16 a, fp16 b) {
    __half2 t(a, b);
    return *reinterpret_cast<uint32_t*>(&t);
}
__device__ __forceinline__ uint4 cvt8(const float* f) {
    return make_uint4(pack_h2(__float2half(f[0]), __float2half(f[1])),
                      pack_h2(__float2half(f[2]), __float2half(f[3])),
                      pack_h2(__float2half(f[4]), __float2half(f[5])),
                      pack_h2(__float2half(f[6]), __float2half(f[7])));
}
__device__ __forceinline__ float sigm(float x) { return 1.f / (1.f + expf(-x)); }

__device__ __forceinline__ void cp_async16(uint32_t dst, const void* src, int pred) {
    int sz = pred ? 16 : 0;
    asm volatile("cp.async.ca.shared.global [%0], [%1], 16, %2;"
                 :: "r"(dst), "l"(src), "r"(sz));
}
__device__ __forceinline__ void cp_commit() {
    asm volatile("cp.async.commit_group;" ::: "memory");
}
__device__ __forceinline__ void cp_wait0() {
    asm volatile("cp.async.wait_group 0;" ::: "memory");
}

// ---------------- fused prep ----------------
#define T8_P1 (512 * 256 / 8)
#define T8_P2 (256 * 512 / 8)
#define T8_WI (2048 * 256 / 8)
#define T8_WH (2048 * 256 / 8)
#define T8_ALL (T8_P1 + T8_P2 + T8_WI + T8_WH)

__global__ void prep_all_kernel(const float* __restrict__ gcnW,
                                const float* __restrict__ wb,
                                const float* __restrict__ gb,
                                const float* __restrict__ bih,
                                const float* __restrict__ bhh,
                                const int* __restrict__ qlc_i32,
                                const float* __restrict__ p1W,
                                const float* __restrict__ p2W,
                                const float* __restrict__ Wih,
                                const float* __restrict__ Whh) {
    int idx = blockIdx.x * blockDim.x + threadIdx.x;
    if (idx == 0) {
        int any = 0;
        for (int i = 1; i < 2 * NB; i += 2) any |= qlc_i32[i];
        g_is64 = (any == 0) ? 1 : 0;
    }
    if (idx < 256 * 128) {
        int j = idx >> 7, e = idx & 127;
        float v = (j < 128) ? gcnW[j * 256 + e] : gcnW[(j - 128) * 256 + 128 + e];
        g_Wph[idx] = __float2half(v);
    }
    if (idx < 256) g_biasproj[idx] = (idx < 128) ? (wb[idx] + gb[idx]) : 0.f;
    if (idx < G4)  g_bsum[idx] = bih[idx] + bhh[idx];

    if (idx < T8_ALL) {
        const float* src;
        fp16* dst;
        int e0;
        if (idx < T8_P1) {
            e0 = idx * 8; src = p1W + e0; dst = g_p1h + e0;
        } else if (idx < T8_P1 + T8_P2) {
            e0 = (idx - T8_P1) * 8; src = p2W + e0; dst = g_p2h + e0;
        } else if (idx < T8_P1 + T8_P2 + T8_WI) {
            e0 = (idx - T8_P1 - T8_P2) * 8; src = Wih + e0; dst = g_Wihh + e0;
        } else {
            e0 = (idx - T8_P1 - T8_P2 - T8_WI) * 8;
            int row = e0 >> 8, col = e0 & 255;
            src = Whh + (size_t)row * 512 + col;
            dst = g_Whhh + e0;
        }
        float4 v0 = *reinterpret_cast<const float4*>(src);
        float4 v1 = *reinterpret_cast<const float4*>(src + 4);
        float f[8] = {v0.x, v0.y, v0.z, v0.w, v1.x, v1.y, v1.z, v1.w};
        *reinterpret_cast<uint4*>(dst) = cvt8(f);
    }
}

// =====================================================================
// proj_mma: g_projh[NSYM,256] = fp16(emb @ Wproj^T + bias)
// B tile prefetched via cp.async, overlapped with A fp32->fp16 convert.
// =====================================================================
#define ROWB 272
#define PA_OFF 0
#define PB_OFF (128 * ROWB)
#define PROJ_SMEM (PB_OFF + 256 * ROWB)   // 104448

__global__ void __launch_bounds__(256, 2)
proj_mma_kernel(const float* __restrict__ emb) {
    extern __shared__ char sm[];
    const uint32_t sbase = smem_u32(sm);
    const int tid = threadIdx.x;
    const int mbase = blockIdx.x * 128;

    // B tile async first (256 rows x 128 fp16 = 4096 16B chunks)
#pragma unroll
    for (int i = 0; i < 16; ++i) {
        int c = tid + i * 256;
        int row = c >> 4, ch = c & 15;
        cp_async16(sbase + PB_OFF + row * ROWB + ch * 16,
                   g_Wph + row * 128 + ch * 8, 1);
    }
    cp_commit();

    // A tile: 128 rows x 128 fp32 -> fp16 (overlaps B's gmem latency)
#pragma unroll
    for (int i = 0; i < 8; ++i) {
        int c = tid + i * 256;
        int row = c >> 4, ch = c & 15;
        int grow = mbase + row;
        uint4 h = make_uint4(0, 0, 0, 0);
        if (grow < NSYM) {
            const float* p = emb + (size_t)grow * 128 + ch * 8;
            float4 v0 = *reinterpret_cast<const float4*>(p);
            float4 v1 = *reinterpret_cast<const float4*>(p + 4);
            float f[8] = {v0.x, v0.y, v0.z, v0.w, v1.x, v1.y, v1.z, v1.w};
            h = cvt8(f);
        }
        *reinterpret_cast<uint4*>(sm + PA_OFF + row * ROWB + ch * 16) = h;
    }
    cp_wait0();
    __syncthreads();

    const int warp = tid >> 5, lane = tid & 31;
    const int wm = warp & 3, wn = warp >> 2;
    const int m0 = wm * 32, n0 = wn * 64;

    const int a_row = (lane & 15);
    const int a_kadd = (lane >> 4) << 3;
    const int b_row = ((lane >> 4) << 3) + (lane & 7);
    const int b_kadd = ((lane >> 3) & 1) << 3;

    for (int half = 0; half < 2; ++half) {
        const uint32_t bofs = PB_OFF + half * 128 * ROWB;

        float acc[2][8][4];
#pragma unroll
        for (int i = 0; i < 2; ++i)
#pragma unroll
            for (int j = 0; j < 8; ++j)
#pragma unroll
                for (int q = 0; q < 4; ++q) acc[i][j][q] = 0.f;

#pragma unroll
        for (int ks = 0; ks < 8; ++ks) {
            const int k0 = ks * 16;
            uint32_t ra[2][4];
#pragma unroll
            for (int mi = 0; mi < 2; ++mi)
                ldmatrix4(sbase + PA_OFF + (m0 + mi * 16 + a_row) * ROWB + (k0 + a_kadd) * 2,
                          ra[mi][0], ra[mi][1], ra[mi][2], ra[mi][3]);
            uint32_t rb[4][4];
#pragma unroll
            for (int np = 0; np < 4; ++np)
                ldmatrix4(sbase + bofs + (n0 + np * 16 + b_row) * ROWB + (k0 + b_kadd) * 2,
                          rb[np][0], rb[np][1], rb[np][2], rb[np][3]);
#pragma unroll
            for (int mi = 0; mi < 2; ++mi)
#pragma unroll
                for (int ni = 0; ni < 8; ++ni)
                    mma16816(acc[mi][ni], ra[mi],
                             rb[ni >> 1][(ni & 1) * 2 + 0], rb[ni >> 1][(ni & 1) * 2 + 1]);
        }

        const int rbase = mbase + m0;
#pragma unroll
        for (int mi = 0; mi < 2; ++mi) {
#pragma unroll
            for (int ni = 0; ni < 8; ++ni) {
                int gcol = half * 128 + n0 + ni * 8 + (lane & 3) * 2;
                float b0 = g_biasproj[gcol], b1 = g_biasproj[gcol + 1];
                int r0 = rbase + mi * 16 + (lane >> 2);
                int r1 = r0 + 8;
                if (r0 < NSYM)
                    *reinterpret_cast<uint32_t*>(g_projh + (size_t)r0 * 256 + gcol) =
                        pack_h2(__float2half(acc[mi][ni][0] + b0),
                                __float2half(acc[mi][ni][1] + b1));
                if (r1 < NSYM)
                    *reinterpret_cast<uint32_t*>(g_projh + (size_t)r1 * 256 + gcol) =
                        pack_h2(__float2half(acc[mi][ni][2] + b0),
                                __float2half(acc[mi][ni][3] + b1));
            }
        }
    }
}

// =====================================================================
// hgemm_small: 64(M) x 128(N) tile, 128 threads, cp.async double-buffered.
// =====================================================================
#define KROWB 144
#define HS_BUF ((64 + 128) * KROWB)
#define HS_A   0
#define HS_B   (64 * KROWB)
#define HS_SMEM (2 * HS_BUF)   // 55296

__global__ void __launch_bounds__(128, 4)
hgemm_small(int M, int N, int K,
            const fp16* __restrict__ A, const fp16* __restrict__ B,
            const float* __restrict__ bias, const float* __restrict__ addMat,
            float* __restrict__ C, fp16* __restrict__ Chi, int doRelu, int colSel) {
    extern __shared__ char sm[];
    const uint32_t sbase = smem_u32(sm);
    const int tid = threadIdx.x;
    const int mtile = blockIdx.y * 64;
    int bx = blockIdx.x;
    if (colSel) bx = (bx & 1) + ((bx >> 1) << 2);
    const int ntile = bx * 128;

    const int warp = tid >> 5, lane = tid & 31;
    const int wm = warp & 1, wn = warp >> 1;
    const int m0 = wm * 32, n0 = wn * 64;

    float acc[2][8][4];
#pragma unroll
    for (int i = 0; i < 2; ++i)
#pragma unroll
        for (int j = 0; j < 8; ++j)
#pragma unroll
            for (int q = 0; q < 4; ++q) acc[i][j][q] = 0.f;

    const int a_row = (lane & 15);
    const int a_kadd = (lane >> 4) << 3;
    const int b_row = ((lane >> 4) << 3) + (lane & 7);
    const int b_kadd = ((lane >> 3) & 1) << 3;

    auto issue_chunk = [&](int kc, int buf) {
        uint32_t dst0 = sbase + buf * HS_BUF;
#pragma unroll
        for (int i = 0; i < 4; ++i) {
            int c = tid + i * 128;
            int row = c >> 3, ch = c & 7;
            int grow = mtile + row;
            int ok = grow < M;
            const fp16* src = A + (size_t)(ok ? grow : 0) * K + kc + ch * 8;
            cp_async16(dst0 + HS_A + row * KROWB + ch * 16, src, ok);
        }
#pragma unroll
        for (int i = 0; i < 8; ++i) {
            int c = tid + i * 128;
            int row = c >> 3, ch = c & 7;
            int grow = ntile + row;
            const fp16* src = B + (size_t)grow * K + kc + ch * 8;
            cp_async16(dst0 + HS_B + row * KROWB + ch * 16, src, 1);
        }
        cp_commit();
    };

    int buf = 0;
    issue_chunk(0, 0);
    cp_wait0();
    __syncthreads();

    for (int kc = 0; kc < K; kc += 64) {
        int has_next = (kc + 64 < K);
        if (has_next) issue_chunk(kc + 64, buf ^ 1);

        const uint32_t cb = sbase + buf * HS_BUF;
#pragma unroll
        for (int ks = 0; ks < 4; ++ks) {
            const int k0 = ks * 16;
            uint32_t ra[2][4];
#pragma unroll
            for (int mi = 0; mi < 2; ++mi)
                ldmatrix4(cb + HS_A + (m0 + mi * 16 + a_row) * KROWB + (k0 + a_kadd) * 2,
                          ra[mi][0], ra[mi][1], ra[mi][2], ra[mi][3]);
            uint32_t rb[4][4];
#pragma unroll
            for (int np = 0; np < 4; ++np)
                ldmatrix4(cb + HS_B + (n0 + np * 16 + b_row) * KROWB + (k0 + b_kadd) * 2,
                          rb[np][0], rb[np][1], rb[np][2], rb[np][3]);
#pragma unroll
            for (int mi = 0; mi < 2; ++mi)
#pragma unroll
                for (int ni = 0; ni < 8; ++ni)
                    mma16816(acc[mi][ni], ra[mi],
                             rb[ni >> 1][(ni & 1) * 2 + 0], rb[ni >> 1][(ni & 1) * 2 + 1]);
        }
        if (has_next) {
            cp_wait0();
            __syncthreads();
            buf ^= 1;
        }
    }

#pragma unroll
    for (int mi = 0; mi < 2; ++mi) {
#pragma unroll
        for (int ni = 0; ni < 8; ++ni) {
            int col = ntile + n0 + ni * 8 + (lane & 3) * 2;
            float b0 = bias ? bias[col] : 0.f;
            float b1 = bias ? bias[col + 1] : 0.f;
#pragma unroll
            for (int half = 0; half < 2; ++half) {
                int r = mtile + m0 + mi * 16 + (lane >> 2) + half * 8;
                if (r >= M) continue;
                float vx = acc[mi][ni][half * 2 + 0] + b0;
                float vy = acc[mi][ni][half * 2 + 1] + b1;
                if (addMat) {
                    vx += addMat[(size_t)r * N + col];
                    vy += addMat[(size_t)r * N + col + 1];
                }
                if (doRelu) { vx = fmaxf(vx, 0.f); vy = fmaxf(vy, 0.f); }
                if (C)
                    *reinterpret_cast<float2*>(C + (size_t)r * N + col) = make_float2(vx, vy);
                if (Chi)
                    *reinterpret_cast<uint32_t*>(Chi + (size_t)r * N + col) =
                        pack_h2(__float2half(vx), __float2half(vy));
            }
        }
    }
}

// ---------------- neighbor encoder: 4-way split-k, 256 threads ----------
__global__ void __launch_bounds__(256)
neighbor_kernel(const void* qlc, const void* qrc, const void* slc, const void* src) {
    __shared__ int sidx[2 * NB];
    __shared__ float red1[256];   // grp 1 partials
    __shared__ float red2[256];   // grp 2 partials
    __shared__ float red3[256];   // grp 3 partials
    int b = blockIdx.x;
    const void* conn;
    int node, off;
    if (b < BQ)                { conn = qlc; node = b;                off = node * DM; }
    else if (b < 2 * BQ)       { conn = qrc; node = b - BQ;           off = node * DM + 128; }
    else if (b < 2 * BQ + FEW) { conn = slc; node = b - 2 * BQ;       off = (BQ + node) * DM; }
    else                       { conn = src; node = b - 2 * BQ - FEW; off = (BQ + node) * DM + 128; }

    int tid = threadIdx.x;
    size_t base = (size_t)node * (2 * NB);
    if (g_is64) {
        const long long* p = (const long long*)conn;
        for (int t = tid; t < 2 * NB; t += 256) sidx[t] = (int)p[base + t];
    } else {
        const int* p = (const int*)conn;
        for (int t = tid; t < 2 * NB; t += 256) sidx[t] = p[base + t];
    }
    __syncthreads();

    const fp16* __restrict__ proj = g_projh;
    const int grp = tid >> 6;          // 0..3: k parity
    const int c2 = (tid & 63) * 2;     // column pair

    float m0 = -INFINITY, m1 = -INFINITY;
    for (int k = grp; k < NB; k += 4) {
        int rel = sidx[2 * k], ent = sidx[2 * k + 1];
        if (rel == PADID || ent == PADID) continue;
        __half2 a = *reinterpret_cast<const __half2*>(proj + (size_t)rel * 256 + c2);
        __half2 e = *reinterpret_cast<const __half2*>(proj + (size_t)ent * 256 + 128 + c2);
        float v0 = __half2float(__low2half(a)) + __half2float(__low2half(e));
        float v1 = __half2float(__high2half(a)) + __half2float(__high2half(e));
        v0 = (v0 > 0.f) ? v0 : 0.1f * v0;
        v1 = (v1 > 0.f) ? v1 : 0.1f * v1;
        m0 = fmaxf(m0, v0);
        m1 = fmaxf(m1, v1);
    }

    if (grp == 1) { red1[c2] = m0; red1[c2 + 1] = m1; }
    if (grp == 2) { red2[c2] = m0; red2[c2 + 1] = m1; }
    if (grp == 3) { red3[c2] = m0; red3[c2 + 1] = m1; }
    __syncthreads();
    if (grp == 0) {
        float f0 = fmaxf(fmaxf(m0, red1[c2]), fmaxf(red2[c2], red3[c2]));
        float f1 = fmaxf(fmaxf(m1, red1[c2 + 1]), fmaxf(red2[c2 + 1], red3[c2 + 1]));
        f0 = tanhf(f0);
        f1 = tanhf(f1);
        *reinterpret_cast<float2*>(g_xcat + off + c2) = make_float2(f0, f1);
        *reinterpret_cast<uint32_t*>(g_xcath + off + c2) =
            pack_h2(__float2half(f0), __float2half(f1));
    }
}

// ---------------- layernorm ----------------
__global__ void ln_kernel(const float* __restrict__ lg, const float* __restrict__ lb) {
    __shared__ float red[256];
    int row = blockIdx.x, t = threadIdx.x;
    float v = g_oenc[row * DM + t];
    red[t] = v;
    __syncthreads();
    for (int s = 128; s > 0; s >>= 1) { if (t < s) red[t] += red[t + s]; __syncthreads(); }
    float mu = red[0] * (1.f / 256.f);
    __syncthreads();
    float d = v - mu;
    red[t] = d * d;
    __syncthreads();
    for (int s = 128; s > 0; s >>= 1) { if (t < s) red[t] += red[t + s]; __syncthreads(); }
    float var = red[0] * (1.f / 256.f);
    float o = d * rsqrtf(var + 1e-5f) * lg[t] + lb[t];
    g_enc[row * DM + t] = o;
    g_ench[row * DM + t] = __float2half(o);
}

// ---------------- fused mean + sconst ----------------
__global__ void sconst2_kernel(const float* __restrict__ Whh) {
    __shared__ float sup[256];
    int t = threadIdx.x;
    float s = 0.f;
    for (int r = 0; r < FEW; ++r) s += g_enc[(BQ + r) * DM + t];
    s *= (1.f / FEW);
    sup[t] = s;
    if (blockIdx.x == 0) g_support[t] = s;
    __syncthreads();

    int warp = t >> 5, lane = t & 31;
#pragma unroll
    for (int gi = 0; gi < 4; ++gi) {
        int gidx = blockIdx.x * 32 + warp * 4 + gi;
        float acc = 0.f;
        for (int i = lane; i < DM; i += 32)
            acc += sup[i] * Whh[(size_t)gidx * 512 + 256 + i];
#pragma unroll
        for (int o = 16; o > 0; o >>= 1) acc += __shfl_down_sync(0xffffffffu, acc, o);
        if (lane == 0) g_sconst[gidx] = acc;
    }
}

// ---------------- LSTM elementwise step (steps 1..3) ----------------
__global__ void lstm_kernel(const float* __restrict__ G, int firstStep) {
    int idx = blockIdx.x * blockDim.x + threadIdx.x;
    if (idx >= BQ * HID) return;
    int n = idx >> 9, j = idx & 511;
    const float* g = G + (size_t)n * G4;
    float gi = g[j], gf = g[512 + j], gg = g[1024 + j], go = g[1536 + j];
    float c  = firstStep ? 0.f : g_c[idx];
    float cn = sigm(gf) * c + sigm(gi) * tanhf(gg);
    g_c[idx] = cn;
    if (j < DM) {
        float hv = g_enc[n * DM + j] + sigm(go) * tanhf(cn);
        g_hh[n * DM + j] = __float2half(hv);
    }
}

// ---------------- last LSTM step fused with final dot ----------------
__global__ void lstm_last_kernel(const float* __restrict__ G, float* __restrict__ out) {
    __shared__ float red[256];
    int n = blockIdx.x, j = threadIdx.x;
    const float* g = G + (size_t)n * G4;
    float gi = g[j], gf = g[512 + j], gg = g[1024 + j], go = g[1536 + j];
    float c  = g_c[n * 512 + j];
    float cn = sigm(gf) * c + sigm(gi) * tanhf(gg);
    float hv = g_enc[n * DM + j] + sigm(go) * tanhf(cn);
    red[j] = hv * g_support[j];
    __syncthreads();
    for (int s = 128; s > 0; s >>= 1) { if (j < s) red[j] += red[j + s]; __syncthreads(); }
    if (j == 0) out[n] = red[0];
}

// ---------------- launch ----------------
extern "C" void kernel_launch(void* const* d_in, const int* in_sizes, int n_in,
                              void* d_out, int out_size) {
    const void* qlc = d_in[0];
    const void* qrc = d_in[1];
    const void* slc = d_in[2];
    const void* src = d_in[3];
    const float* emb  = (const float*)d_in[8];
    const float* gcnW = (const float*)d_in[9];
    const float* wb   = (const float*)d_in[10];
    const float* gb   = (const float*)d_in[11];
    const float* p1W  = (const float*)d_in[12];
    const float* p1b  = (const float*)d_in[13];
    const float* p2W  = (const float*)d_in[14];
    const float* p2b  = (const float*)d_in[15];
    const float* lng  = (const float*)d_in[16];
    const float* lnb  = (const float*)d_in[17];
    const float* Wih  = (const float*)d_in[18];
    const float* Whh  = (const float*)d_in[19];
    const float* bih  = (const float*)d_in[20];
    const float* bhh  = (const float*)d_in[21];

    fp16 *p1h, *p2h, *Wihh, *Whhh, *xcath, *hench, *ench, *hh;
    float *xcat, *oenc, *sconst, *qWihb, *gates, *bsum;
    cudaGetSymbolAddress((void**)&p1h,    g_p1h);
    cudaGetSymbolAddress((void**)&p2h,    g_p2h);
    cudaGetSymbolAddress((void**)&Wihh,   g_Wihh);
    cudaGetSymbolAddress((void**)&Whhh,   g_Whhh);
    cudaGetSymbolAddress((void**)&xcath,  g_xcath);
    cudaGetSymbolAddress((void**)&hench,  g_hench);
    cudaGetSymbolAddress((void**)&ench,   g_ench);
    cudaGetSymbolAddress((void**)&hh,     g_hh);
    cudaGetSymbolAddress((void**)&xcat,   g_xcat);
    cudaGetSymbolAddress((void**)&oenc,   g_oenc);
    cudaGetSymbolAddress((void**)&sconst, g_sconst);
    cudaGetSymbolAddress((void**)&qWihb,  g_qWihb);
    cudaGetSymbolAddress((void**)&gates,  g_gates);
    cudaGetSymbolAddress((void**)&bsum,   g_bsum);

    prep_all_kernel<<<(T8_ALL + 255) / 256, 256>>>(
        gcnW, wb, gb, bih, bhh, (const int*)qlc, p1W, p2W, Wih, Whh);

    cudaFuncSetAttribute(proj_mma_kernel,
                         cudaFuncAttributeMaxDynamicSharedMemorySize, PROJ_SMEM);
    proj_mma_kernel<<<(NSYM + 127) / 128, 256, PROJ_SMEM>>>(emb);

    neighbor_kernel<<<2 * BQ + 2 * FEW, 256>>>(qlc, qrc, slc, src);

    cudaFuncSetAttribute(hgemm_small,
                         cudaFuncAttributeMaxDynamicSharedMemorySize, HS_SMEM);

    // support encoder
    hgemm_small<<<dim3(512 / 128, (NROWS + 63) / 64), 128, HS_SMEM>>>(
        NROWS, 512, 256, xcath, p1h, p1b, nullptr, nullptr, hench, 1, 0);
    hgemm_small<<<dim3(256 / 128, (NROWS + 63) / 64), 128, HS_SMEM>>>(
        NROWS, 256, 512, hench, p2h, p2b, xcat, oenc, nullptr, 0, 0);
    ln_kernel<<<NROWS, 256>>>(lng, lnb);

    sconst2_kernel<<<G4 / 32, 256>>>(Whh);

    // qWihb = enc@Wih^T + (b_ih + b_hh)
    hgemm_small<<<dim3(G4 / 128, BQ / 64), 128, HS_SMEM>>>(
        BQ, G4, 256, ench, Wihh, bsum, nullptr, qWihb, nullptr, 0, 0);

    lstm_kernel<<<(BQ * HID + 255) / 256, 256>>>(qWihb, 1);

    for (int s = 1; s < 3; ++s) {
        hgemm_small<<<dim3(G4 / 128, BQ / 64), 128, HS_SMEM>>>(
            BQ, G4, 256, hh, Whhh, sconst, qWihb, gates, nullptr, 0, 0);
        lstm_kernel<<<(BQ * HID + 255) / 256, 256>>>(gates, 0);
    }
    // step-4 gates: only the 8 N-tiles consumed by lstm_last
    hgemm_small<<<dim3(8, BQ / 64), 128, HS_SMEM>>>(
        BQ, G4, 256, hh, Whhh, sconst, qWihb, gates, nullptr, 0, 1);
    lstm_last_kernel<<<BQ, 256>>>(gates, (float*)d_out);
}